// round 4
// baseline (speedup 1.0000x reference)
#include <cuda_runtime.h>
#include <cuda_bf16.h>
#include <cstdint>

// Problem constants
#define BB 2
#define SS 2048
#define DD 1024
#define HH 16
#define HD 64
#define NTOK (BB*SS)   // 4096

// ---------------------------------------------------------------------------
// Scratch (__device__ globals per allocation rules).
// ---------------------------------------------------------------------------
__device__ float g_q[NTOK*DD];
__device__ float g_k[NTOK*DD];
__device__ __nv_bfloat16 g_xhi[NTOK*DD];
__device__ __nv_bfloat16 g_xlo[NTOK*DD];
__device__ __nv_bfloat16 g_ohi[NTOK*DD];
__device__ __nv_bfloat16 g_olo[NTOK*DD];
__device__ __nv_bfloat16 g_vhi[NTOK*DD];
__device__ __nv_bfloat16 g_vlo[NTOK*DD];
__device__ __nv_bfloat16 g_qhi[NTOK*DD];
__device__ __nv_bfloat16 g_qlo[NTOK*DD];
__device__ __nv_bfloat16 g_khi[NTOK*DD];
__device__ __nv_bfloat16 g_klo[NTOK*DD];
__device__ __nv_bfloat16 g_whi[4][DD*DD];
__device__ __nv_bfloat16 g_wlo[4][DD*DD];

// ---------------------------------------------------------------------------
// Helpers (sm_80-era instructions only — NO tcgen05/arch-a features)
// ---------------------------------------------------------------------------
__device__ __forceinline__ uint32_t smem_u32(const void* p) {
    uint32_t a;
    asm("{ .reg .u64 t; cvta.to.shared.u64 t, %1; cvt.u32.u64 %0, t; }"
        : "=r"(a) : "l"(p));
    return a;
}
__device__ __forceinline__ void cpa16(uint32_t dst, const void* src) {
    asm volatile("cp.async.cg.shared.global [%0], [%1], 16;" :: "r"(dst), "l"(src));
}
#define CP_COMMIT() asm volatile("cp.async.commit_group;" ::: "memory")
#define CP_WAIT(n)  asm volatile("cp.async.wait_group %0;" :: "n"(n) : "memory")

__device__ __forceinline__ void ldm_x4(uint32_t* r, uint32_t addr) {
    asm volatile("ldmatrix.sync.aligned.m8n8.x4.shared.b16 {%0,%1,%2,%3}, [%4];"
                 : "=r"(r[0]), "=r"(r[1]), "=r"(r[2]), "=r"(r[3]) : "r"(addr));
}
__device__ __forceinline__ void ldm_x4_t(uint32_t* r, uint32_t addr) {
    asm volatile("ldmatrix.sync.aligned.m8n8.x4.trans.shared.b16 {%0,%1,%2,%3}, [%4];"
                 : "=r"(r[0]), "=r"(r[1]), "=r"(r[2]), "=r"(r[3]) : "r"(addr));
}
__device__ __forceinline__ void mma16816(float* d, const uint32_t* a,
                                         uint32_t b0, uint32_t b1) {
    asm volatile(
        "mma.sync.aligned.m16n8k16.row.col.f32.bf16.bf16.f32 "
        "{%0,%1,%2,%3}, {%4,%5,%6,%7}, {%8,%9}, {%0,%1,%2,%3};"
        : "+f"(d[0]), "+f"(d[1]), "+f"(d[2]), "+f"(d[3])
        : "r"(a[0]), "r"(a[1]), "r"(a[2]), "r"(a[3]), "r"(b0), "r"(b1));
}
__device__ __forceinline__ uint32_t pack_bf(float lo, float hi) {
    __nv_bfloat162 t = __floats2bfloat162_rn(lo, hi);
    return *(uint32_t*)&t;
}
// swizzled byte offset within a tile of 128B rows (64 bf16), 16B granules
#define SW(r, g) ((r)*128 + ((((g) ^ ((r)&7))) << 4))

// ---------------------------------------------------------------------------
// fp32 -> bf16 hi/lo split. dst: 0=X, 2..5=W[0..3]
// ---------------------------------------------------------------------------
__global__ __launch_bounds__(256) void conv_split_kernel(const float* __restrict__ src,
                                                         int dst)
{
    __nv_bfloat16 *hi, *lo;
    if (dst == 0) { hi = g_xhi; lo = g_xlo; }
    else          { hi = g_whi[dst-2]; lo = g_wlo[dst-2]; }

    int i = (blockIdx.x * 256 + threadIdx.x) * 4;
    float4 v = *(const float4*)(src + i);
    __nv_bfloat16 h0 = __float2bfloat16_rn(v.x);
    __nv_bfloat16 h1 = __float2bfloat16_rn(v.y);
    __nv_bfloat16 h2 = __float2bfloat16_rn(v.z);
    __nv_bfloat16 h3 = __float2bfloat16_rn(v.w);
    __nv_bfloat16 l0 = __float2bfloat16_rn(v.x - __bfloat162float(h0));
    __nv_bfloat16 l1 = __float2bfloat16_rn(v.y - __bfloat162float(h1));
    __nv_bfloat16 l2 = __float2bfloat16_rn(v.z - __bfloat162float(h2));
    __nv_bfloat16 l3 = __float2bfloat16_rn(v.w - __bfloat162float(h3));
    ((__nv_bfloat162*)(hi + i))[0] = __halves2bfloat162(h0, h1);
    ((__nv_bfloat162*)(hi + i))[1] = __halves2bfloat162(h2, h3);
    ((__nv_bfloat162*)(lo + i))[0] = __halves2bfloat162(l0, l1);
    ((__nv_bfloat162*)(lo + i))[1] = __halves2bfloat162(l2, l3);
}

// ---------------------------------------------------------------------------
// HMMA GEMM: Y[m,n] = sum_k A[m,k]*B[n,k] + bias[n], bf16x3 split
// (pass 0: Ahi*Bhi, 1: Ahi*Blo, 2: Alo*Bhi). CTA 128x128, 8 warps (64x32
// warp tile), K-chunk 64, 2-stage cp.async, ONE syncthreads per chunk:
//   wait(0) -> sync -> issue load(c+1) -> compute(c)
// Epilogue: fp32 (Yf != null) or fused bf16 hi/lo split (Yhi/Ylo).
// ---------------------------------------------------------------------------
#define GEMM_SMEM (2*32768)

__device__ __forceinline__ void gemm_hmma(
    const __nv_bfloat16* __restrict__ Ahi, const __nv_bfloat16* __restrict__ Alo,
    const __nv_bfloat16* __restrict__ Bhi, const __nv_bfloat16* __restrict__ Blo,
    const float* __restrict__ bias, float* __restrict__ Yf,
    __nv_bfloat16* __restrict__ Yhi, __nv_bfloat16* __restrict__ Ylo)
{
    extern __shared__ char sm[];
    const uint32_t sb = smem_u32(sm);
    const int tid = threadIdx.x;
    const int wid = tid >> 5, lane = tid & 31;
    const int warp_m = (wid >> 2) << 6;     // 0 / 64
    const int warp_n = (wid & 3) << 5;      // 0..96
    const int bm = blockIdx.y * 128, bn = blockIdx.x * 128;
    const int sub = lane >> 3, l7 = lane & 7;

    float acc[4][4][4];
#pragma unroll
    for (int mt = 0; mt < 4; mt++)
#pragma unroll
        for (int nt = 0; nt < 4; nt++)
#pragma unroll
            for (int j = 0; j < 4; j++) acc[mt][nt][j] = 0.f;

    // chunk kk (0..47): pass = kk>>4, c = kk&15, kt = c*64
    auto load_chunk = [&](int kk, int st) {
        const int p = kk >> 4, c = kk & 15;
        const __nv_bfloat16* As = (p == 2) ? Alo : Ahi;
        const __nv_bfloat16* Bs = (p == 1) ? Blo : Bhi;
        const int kt = c * 64;
        const uint32_t stA = sb + st * 32768;
        const uint32_t stB = stA + 16384;
#pragma unroll
        for (int i = 0; i < 4; i++) {
            int gid = i * 256 + tid;
            int r = gid >> 3, g = gid & 7;
            cpa16(stA + SW(r, g), As + (size_t)(bm + r) * DD + kt + g * 8);
        }
#pragma unroll
        for (int i = 0; i < 4; i++) {
            int gid = i * 256 + tid;
            int r = gid >> 3, g = gid & 7;
            cpa16(stB + SW(r, g), Bs + (size_t)(bn + r) * DD + kt + g * 8);
        }
        CP_COMMIT();
    };

    load_chunk(0, 0);

    for (int kk = 0; kk < 48; kk++) {
        const int st = kk & 1;
        CP_WAIT(0);
        __syncthreads();
        if (kk < 47) load_chunk(kk + 1, st ^ 1);

        const uint32_t stA = sb + st * 32768;
        const uint32_t stB = stA + 16384;
#pragma unroll
        for (int ks = 0; ks < 4; ks++) {
            const int g = ks * 2 + (sub >> 1);
            uint32_t a[4][4];
#pragma unroll
            for (int mt = 0; mt < 4; mt++) {
                int row = warp_m + mt * 16 + ((sub & 1) << 3) + l7;
                ldm_x4(a[mt], stA + SW(row, g));
            }
            uint32_t bf[4][2];
#pragma unroll
            for (int hb = 0; hb < 2; hb++) {
                uint32_t r4[4];
                int row = warp_n + hb * 16 + ((sub & 1) << 3) + l7;
                ldm_x4(r4, stB + SW(row, g));
                bf[hb*2][0]   = r4[0]; bf[hb*2][1]   = r4[2];
                bf[hb*2+1][0] = r4[1]; bf[hb*2+1][1] = r4[3];
            }
#pragma unroll
            for (int mt = 0; mt < 4; mt++)
#pragma unroll
                for (int nt = 0; nt < 4; nt++)
                    mma16816(acc[mt][nt], a[mt], bf[nt][0], bf[nt][1]);
        }
    }

    // Epilogue
    const int rq = lane >> 2, cq = (lane & 3) << 1;
#pragma unroll
    for (int mt = 0; mt < 4; mt++) {
        int row = bm + warp_m + mt * 16 + rq;
#pragma unroll
        for (int nt = 0; nt < 4; nt++) {
            int col = bn + warp_n + nt * 8 + cq;
            float b0 = __ldg(bias + col), b1 = __ldg(bias + col + 1);
            float y00 = acc[mt][nt][0] + b0, y01 = acc[mt][nt][1] + b1;
            float y10 = acc[mt][nt][2] + b0, y11 = acc[mt][nt][3] + b1;
            if (Yf) {
                *(float2*)(Yf + (size_t)row * DD + col)       = make_float2(y00, y01);
                *(float2*)(Yf + (size_t)(row + 8) * DD + col) = make_float2(y10, y11);
            } else {
                __nv_bfloat162 h0 = __floats2bfloat162_rn(y00, y01);
                __nv_bfloat162 h1 = __floats2bfloat162_rn(y10, y11);
                __nv_bfloat162 l0 = __floats2bfloat162_rn(y00 - __bfloat162float(h0.x),
                                                          y01 - __bfloat162float(h0.y));
                __nv_bfloat162 l1 = __floats2bfloat162_rn(y10 - __bfloat162float(h1.x),
                                                          y11 - __bfloat162float(h1.y));
                *(__nv_bfloat162*)(Yhi + (size_t)row * DD + col)       = h0;
                *(__nv_bfloat162*)(Yhi + (size_t)(row + 8) * DD + col) = h1;
                *(__nv_bfloat162*)(Ylo + (size_t)row * DD + col)       = l0;
                *(__nv_bfloat162*)(Ylo + (size_t)(row + 8) * DD + col) = l1;
            }
        }
    }
}

__global__ __launch_bounds__(256) void qkv_hmma_kernel(
    const float* __restrict__ qb, const float* __restrict__ kb,
    const float* __restrict__ vb)
{
    const int z = blockIdx.z;
    if (z == 0)      gemm_hmma(g_xhi, g_xlo, g_whi[0], g_wlo[0], qb, g_q, 0, 0);
    else if (z == 1) gemm_hmma(g_xhi, g_xlo, g_whi[1], g_wlo[1], kb, g_k, 0, 0);
    else             gemm_hmma(g_xhi, g_xlo, g_whi[2], g_wlo[2], vb, 0, g_vhi, g_vlo);
}
__global__ __launch_bounds__(256) void oproj_hmma_kernel(
    const float* __restrict__ ob, float* __restrict__ out)
{
    gemm_hmma(g_ohi, g_olo, g_whi[3], g_wlo[3], ob, out, 0, 0);
}

// ---------------------------------------------------------------------------
// Per-head LayerNorm on Q (x0.125 softmax scale folded) and K.
// Reads fp32 g_q/g_k, writes bf16 hi/lo pairs. One warp per 64-elem row.
// ---------------------------------------------------------------------------
__global__ __launch_bounds__(256) void ln_kernel(
    const float* __restrict__ qg, const float* __restrict__ qb,
    const float* __restrict__ kg, const float* __restrict__ kb)
{
    const int warp = threadIdx.x >> 5;
    const int lane = threadIdx.x & 31;
    int row = blockIdx.x * 8 + warp;
    const int NR = BB*SS*HH;

    const float* buf; const float* g; const float* b;
    __nv_bfloat16 *hi, *lo;
    float scale;
    if (row < NR) { buf = g_q; g = qg; b = qb; hi = g_qhi; lo = g_qlo; scale = 0.125f; }
    else { buf = g_k; g = kg; b = kb; hi = g_khi; lo = g_klo; scale = 1.f; row -= NR; }

    const float* p = buf + (size_t)row * HD;
    float x0 = p[lane], x1 = p[lane + 32];

    float s = x0 + x1;
#pragma unroll
    for (int off = 16; off; off >>= 1) s += __shfl_xor_sync(~0u, s, off);
    float mu = s * (1.f / 64.f);

    float d0 = x0 - mu, d1 = x1 - mu;
    float vv = d0*d0 + d1*d1;
#pragma unroll
    for (int off = 16; off; off >>= 1) vv += __shfl_xor_sync(~0u, vv, off);
    float rstd = rsqrtf(vv * (1.f / 64.f) + 1e-5f);

    float y0 = (d0 * rstd * g[lane]      + b[lane])      * scale;
    float y1 = (d1 * rstd * g[lane + 32] + b[lane + 32]) * scale;
    __nv_bfloat16 h0 = __float2bfloat16_rn(y0);
    __nv_bfloat16 h1 = __float2bfloat16_rn(y1);
    size_t off0 = (size_t)row * HD + lane;
    hi[off0]      = h0;
    hi[off0 + 32] = h1;
    lo[off0]      = __float2bfloat16_rn(y0 - __bfloat162float(h0));
    lo[off0 + 32] = __float2bfloat16_rn(y1 - __bfloat162float(h1));
}

// ---------------------------------------------------------------------------
// Flash attention, HMMA bf16x3. 256 threads = 8 warps, q-tile 128 rows,
// warp w owns rows [w*16, w*16+16). K/V hi/lo double-buffered, one
// syncthreads per chunk. Output written directly as bf16 hi/lo split.
// Dynamic smem 96KB: Qhi 16K, Qlo 16K, 2 stages x (KH,KL,VH,VL 8K each).
// ---------------------------------------------------------------------------
#define FLASH_SMEM (32768 + 2*32768)

__global__ __launch_bounds__(256, 2) void flash_hmma_kernel()
{
    extern __shared__ char fsm[];
    const uint32_t sb = smem_u32(fsm);
    const uint32_t QH = sb, QL = sb + 16384;

    const int tid = threadIdx.x;
    const int wid = tid >> 5, lane = tid & 31;
    const int sub = lane >> 3, l7 = lane & 7;
    const int rq = lane >> 2, cq = (lane & 3) << 1;
    const int b = blockIdx.z, h = blockIdx.y;
    const int q0 = blockIdx.x * 128;
    const size_t hbase = (size_t)b * SS * DD + (size_t)h * HD;

    // Load Q hi/lo tiles (128 rows) once
#pragma unroll
    for (int i = 0; i < 4; i++) {
        int gid = i * 256 + tid;
        int r = gid >> 3, g = gid & 7;
        size_t src = hbase + (size_t)(q0 + r) * DD + g * 8;
        cpa16(QH + SW(r, g), g_qhi + src);
        cpa16(QL + SW(r, g), g_qlo + src);
    }
    CP_COMMIT();

    const __nv_bfloat16* kvsrc[4] = { g_khi, g_klo, g_vhi, g_vlo };
    auto load_kv = [&](int c0, int st) {
        const uint32_t stage = sb + 32768 + st * 32768;
#pragma unroll
        for (int t = 0; t < 4; t++) {
            const uint32_t dstt = stage + t * 8192;
#pragma unroll
            for (int i = 0; i < 2; i++) {
                int gid = i * 256 + tid;
                int r = gid >> 3, g = gid & 7;
                cpa16(dstt + SW(r, g),
                      kvsrc[t] + hbase + (size_t)(c0 + r) * DD + g * 8);
            }
        }
        CP_COMMIT();
    };

    load_kv(0, 0);

    float o[8][4];
#pragma unroll
    for (int nt = 0; nt < 8; nt++)
#pragma unroll
        for (int j = 0; j < 4; j++) o[nt][j] = 0.f;
    float m0 = -1e30f, m1 = -1e30f, l0 = 0.f, l1 = 0.f;

    for (int cidx = 0; cidx < SS / 64; cidx++) {
        const int st = cidx & 1;
        CP_WAIT(0);
        __syncthreads();
        if (cidx + 1 < SS / 64) load_kv((cidx + 1) * 64, st ^ 1);

        const uint32_t stage = sb + 32768 + st * 32768;
        const uint32_t KH = stage, KL = stage + 8192,
                       VH = stage + 16384, VL = stage + 24576;

        // ---- S = Q' @ K^T (3-pass bf16 split) ----
        float s[8][4];
#pragma unroll
        for (int nt = 0; nt < 8; nt++)
#pragma unroll
            for (int j = 0; j < 4; j++) s[nt][j] = 0.f;

#pragma unroll
        for (int pass = 0; pass < 3; pass++) {
            const uint32_t Qb = (pass < 2) ? QH : QL;
            const uint32_t Kb = (pass == 1) ? KL : KH;
#pragma unroll
            for (int ks = 0; ks < 4; ks++) {
                const int g = ks * 2 + (sub >> 1);
                uint32_t a[4];
                {
                    int row = wid * 16 + ((sub & 1) << 3) + l7;
                    ldm_x4(a, Qb + SW(row, g));
                }
#pragma unroll
                for (int nb = 0; nb < 4; nb++) {
                    uint32_t r4[4];
                    int row = nb * 16 + ((sub & 1) << 3) + l7;
                    ldm_x4(r4, Kb + SW(row, g));
                    mma16816(s[nb*2],   a, r4[0], r4[2]);
                    mma16816(s[nb*2+1], a, r4[1], r4[3]);
                }
            }
        }

        // ---- online softmax ----
        float rmax0 = -1e30f, rmax1 = -1e30f;
#pragma unroll
        for (int nt = 0; nt < 8; nt++) {
            rmax0 = fmaxf(rmax0, fmaxf(s[nt][0], s[nt][1]));
            rmax1 = fmaxf(rmax1, fmaxf(s[nt][2], s[nt][3]));
        }
        rmax0 = fmaxf(rmax0, __shfl_xor_sync(~0u, rmax0, 1));
        rmax0 = fmaxf(rmax0, __shfl_xor_sync(~0u, rmax0, 2));
        rmax1 = fmaxf(rmax1, __shfl_xor_sync(~0u, rmax1, 1));
        rmax1 = fmaxf(rmax1, __shfl_xor_sync(~0u, rmax1, 2));

        float mn0 = fmaxf(m0, rmax0), mn1 = fmaxf(m1, rmax1);
        float corr0 = __expf(m0 - mn0), corr1 = __expf(m1 - mn1);
        m0 = mn0; m1 = mn1;

        float rs0 = 0.f, rs1 = 0.f;
#pragma unroll
        for (int nt = 0; nt < 8; nt++) {
            s[nt][0] = __expf(s[nt][0] - m0);
            s[nt][1] = __expf(s[nt][1] - m0);
            s[nt][2] = __expf(s[nt][2] - m1);
            s[nt][3] = __expf(s[nt][3] - m1);
            rs0 += s[nt][0] + s[nt][1];
            rs1 += s[nt][2] + s[nt][3];
        }
        rs0 += __shfl_xor_sync(~0u, rs0, 1); rs0 += __shfl_xor_sync(~0u, rs0, 2);
        rs1 += __shfl_xor_sync(~0u, rs1, 1); rs1 += __shfl_xor_sync(~0u, rs1, 2);
        l0 = l0 * corr0 + rs0;
        l1 = l1 * corr1 + rs1;
#pragma unroll
        for (int nt = 0; nt < 8; nt++) {
            o[nt][0] *= corr0; o[nt][1] *= corr0;
            o[nt][2] *= corr1; o[nt][3] *= corr1;
        }

        // ---- P -> A-fragments (hi/lo), in-register ----
        uint32_t phi[4][4], plo[4][4];
#pragma unroll
        for (int kvt = 0; kvt < 4; kvt++) {
            const float* t0 = s[kvt*2];
            const float* t1 = s[kvt*2+1];
            phi[kvt][0] = pack_bf(t0[0], t0[1]);
            phi[kvt][1] = pack_bf(t0[2], t0[3]);
            phi[kvt][2] = pack_bf(t1[0], t1[1]);
            phi[kvt][3] = pack_bf(t1[2], t1[3]);
            __nv_bfloat162 h0 = *(__nv_bfloat162*)&phi[kvt][0];
            __nv_bfloat162 h1 = *(__nv_bfloat162*)&phi[kvt][1];
            __nv_bfloat162 h2 = *(__nv_bfloat162*)&phi[kvt][2];
            __nv_bfloat162 h3 = *(__nv_bfloat162*)&phi[kvt][3];
            plo[kvt][0] = pack_bf(t0[0] - __bfloat162float(h0.x),
                                  t0[1] - __bfloat162float(h0.y));
            plo[kvt][1] = pack_bf(t0[2] - __bfloat162float(h1.x),
                                  t0[3] - __bfloat162float(h1.y));
            plo[kvt][2] = pack_bf(t1[0] - __bfloat162float(h2.x),
                                  t1[1] - __bfloat162float(h2.y));
            plo[kvt][3] = pack_bf(t1[2] - __bfloat162float(h3.x),
                                  t1[3] - __bfloat162float(h3.y));
        }

        // ---- O += P @ V (3-pass, ldmatrix.trans on V) ----
#pragma unroll
        for (int pass = 0; pass < 3; pass++) {
            const uint32_t (*Pa)[4] = (pass < 2) ? phi : plo;
            const uint32_t Vb = (pass == 1) ? VL : VH;
#pragma unroll
            for (int kvt = 0; kvt < 4; kvt++) {
#pragma unroll
                for (int db = 0; db < 4; db++) {
                    uint32_t r4[4];
                    int row = kvt * 16 + ((sub & 1) << 3) + l7;
                    int g = db * 2 + (sub >> 1);
                    ldm_x4_t(r4, Vb + SW(row, g));
                    mma16816(o[db*2],   Pa[kvt], r4[0], r4[1]);
                    mma16816(o[db*2+1], Pa[kvt], r4[2], r4[3]);
                }
            }
        }
    }

    // ---- finalize: divide by l, write bf16 hi/lo split directly ----
    float inv0 = 1.f / l0, inv1 = 1.f / l1;
    int row0 = q0 + wid * 16 + rq;
#pragma unroll
    for (int nt = 0; nt < 8; nt++) {
        int col = nt * 8 + cq;
        float y00 = o[nt][0] * inv0, y01 = o[nt][1] * inv0;
        float y10 = o[nt][2] * inv1, y11 = o[nt][3] * inv1;
        __nv_bfloat162 h0 = __floats2bfloat162_rn(y00, y01);
        __nv_bfloat162 h1 = __floats2bfloat162_rn(y10, y11);
        __nv_bfloat162 lo0 = __floats2bfloat162_rn(y00 - __bfloat162float(h0.x),
                                                   y01 - __bfloat162float(h0.y));
        __nv_bfloat162 lo1 = __floats2bfloat162_rn(y10 - __bfloat162float(h1.x),
                                                   y11 - __bfloat162float(h1.y));
        *(__nv_bfloat162*)(g_ohi + hbase + (size_t)row0 * DD + col)       = h0;
        *(__nv_bfloat162*)(g_ohi + hbase + (size_t)(row0 + 8) * DD + col) = h1;
        *(__nv_bfloat162*)(g_olo + hbase + (size_t)row0 * DD + col)       = lo0;
        *(__nv_bfloat162*)(g_olo + hbase + (size_t)(row0 + 8) * DD + col) = lo1;
    }
}

// ---------------------------------------------------------------------------
extern "C" void kernel_launch(void* const* d_in, const int* in_sizes, int n_in,
                              void* d_out, int out_size)
{
    const float* x   = (const float*)d_in[0];
    const float* qw  = (const float*)d_in[1];
    const float* qb  = (const float*)d_in[2];
    const float* kw  = (const float*)d_in[3];
    const float* kb  = (const float*)d_in[4];
    const float* vw  = (const float*)d_in[5];
    const float* vb  = (const float*)d_in[6];
    const float* ow  = (const float*)d_in[7];
    const float* ob  = (const float*)d_in[8];
    const float* qlg = (const float*)d_in[9];
    const float* qlb = (const float*)d_in[10];
    const float* klg = (const float*)d_in[11];
    const float* klb = (const float*)d_in[12];
    float* out = (float*)d_out;

    cudaFuncSetAttribute(qkv_hmma_kernel,
                         cudaFuncAttributeMaxDynamicSharedMemorySize, GEMM_SMEM);
    cudaFuncSetAttribute(oproj_hmma_kernel,
                         cudaFuncAttributeMaxDynamicSharedMemorySize, GEMM_SMEM);
    cudaFuncSetAttribute(flash_hmma_kernel,
                         cudaFuncAttributeMaxDynamicSharedMemorySize, FLASH_SMEM);

    // fp32 -> bf16 hi/lo splits (X + 4 weights)
    conv_split_kernel<<<NTOK*DD/1024, 256>>>(x,  0);
    conv_split_kernel<<<DD*DD/1024,  256>>>(qw, 2);
    conv_split_kernel<<<DD*DD/1024,  256>>>(kw, 3);
    conv_split_kernel<<<DD*DD/1024,  256>>>(vw, 4);
    conv_split_kernel<<<DD*DD/1024,  256>>>(ow, 5);

    qkv_hmma_kernel<<<dim3(DD/128, NTOK/128, 3), 256, GEMM_SMEM>>>(qb, kb, vb);
    ln_kernel<<<(2 * BB * SS * HH) / 8, 256>>>(qlg, qlb, klg, klb);
    flash_hmma_kernel<<<dim3(SS/128, HH, BB), 256, FLASH_SMEM>>>();
    oproj_hmma_kernel<<<dim3(DD/128, NTOK/128), 256, GEMM_SMEM>>>(ob, out);
}

// round 5
// speedup vs baseline: 1.0549x; 1.0549x over previous
#include <cuda_runtime.h>
#include <cuda_bf16.h>
#include <cstdint>

// Problem constants
#define BB 2
#define SS 2048
#define DD 1024
#define HH 16
#define HD 64
#define NTOK (BB*SS)   // 4096

// ---------------------------------------------------------------------------
// Scratch (__device__ globals per allocation rules).
// ---------------------------------------------------------------------------
__device__ float g_q[NTOK*DD];
__device__ float g_k[NTOK*DD];
__device__ __nv_bfloat16 g_xhi[NTOK*DD];
__device__ __nv_bfloat16 g_xlo[NTOK*DD];
__device__ __nv_bfloat16 g_ohi[NTOK*DD];
__device__ __nv_bfloat16 g_olo[NTOK*DD];
__device__ __nv_bfloat16 g_vhi[NTOK*DD];
__device__ __nv_bfloat16 g_vlo[NTOK*DD];
__device__ __nv_bfloat16 g_qhi[NTOK*DD];
__device__ __nv_bfloat16 g_qlo[NTOK*DD];
__device__ __nv_bfloat16 g_khi[NTOK*DD];
__device__ __nv_bfloat16 g_klo[NTOK*DD];
__device__ __nv_bfloat16 g_whi[4][DD*DD];
__device__ __nv_bfloat16 g_wlo[4][DD*DD];

// ---------------------------------------------------------------------------
// Helpers (sm_80-era instructions only)
// ---------------------------------------------------------------------------
__device__ __forceinline__ uint32_t smem_u32(const void* p) {
    uint32_t a;
    asm("{ .reg .u64 t; cvta.to.shared.u64 t, %1; cvt.u32.u64 %0, t; }"
        : "=r"(a) : "l"(p));
    return a;
}
__device__ __forceinline__ void cpa16(uint32_t dst, const void* src) {
    asm volatile("cp.async.cg.shared.global [%0], [%1], 16;" :: "r"(dst), "l"(src));
}
#define CP_COMMIT() asm volatile("cp.async.commit_group;" ::: "memory")
#define CP_WAIT(n)  asm volatile("cp.async.wait_group %0;" :: "n"(n) : "memory")

__device__ __forceinline__ void ldm_x4(uint32_t* r, uint32_t addr) {
    asm volatile("ldmatrix.sync.aligned.m8n8.x4.shared.b16 {%0,%1,%2,%3}, [%4];"
                 : "=r"(r[0]), "=r"(r[1]), "=r"(r[2]), "=r"(r[3]) : "r"(addr));
}
__device__ __forceinline__ void ldm_x4_t(uint32_t* r, uint32_t addr) {
    asm volatile("ldmatrix.sync.aligned.m8n8.x4.trans.shared.b16 {%0,%1,%2,%3}, [%4];"
                 : "=r"(r[0]), "=r"(r[1]), "=r"(r[2]), "=r"(r[3]) : "r"(addr));
}
__device__ __forceinline__ void mma16816(float* d, const uint32_t* a,
                                         uint32_t b0, uint32_t b1) {
    asm volatile(
        "mma.sync.aligned.m16n8k16.row.col.f32.bf16.bf16.f32 "
        "{%0,%1,%2,%3}, {%4,%5,%6,%7}, {%8,%9}, {%0,%1,%2,%3};"
        : "+f"(d[0]), "+f"(d[1]), "+f"(d[2]), "+f"(d[3])
        : "r"(a[0]), "r"(a[1]), "r"(a[2]), "r"(a[3]), "r"(b0), "r"(b1));
}
__device__ __forceinline__ uint32_t pack_bf(float lo, float hi) {
    __nv_bfloat162 t = __floats2bfloat162_rn(lo, hi);
    return *(uint32_t*)&t;
}
// swizzled byte offset within a tile of 128B rows, 16B granules g=0..7
#define SW(r, g) ((r)*128 + ((((g) ^ ((r)&7))) << 4))

// ---------------------------------------------------------------------------
// fp32 -> bf16 hi/lo split. dst: 0=X, 2..5=W[0..3]
// ---------------------------------------------------------------------------
__global__ __launch_bounds__(256) void conv_split_kernel(const float* __restrict__ src,
                                                         int dst)
{
    __nv_bfloat16 *hi, *lo;
    if (dst == 0) { hi = g_xhi; lo = g_xlo; }
    else          { hi = g_whi[dst-2]; lo = g_wlo[dst-2]; }

    int i = (blockIdx.x * 256 + threadIdx.x) * 4;
    float4 v = *(const float4*)(src + i);
    __nv_bfloat16 h0 = __float2bfloat16_rn(v.x);
    __nv_bfloat16 h1 = __float2bfloat16_rn(v.y);
    __nv_bfloat16 h2 = __float2bfloat16_rn(v.z);
    __nv_bfloat16 h3 = __float2bfloat16_rn(v.w);
    __nv_bfloat16 l0 = __float2bfloat16_rn(v.x - __bfloat162float(h0));
    __nv_bfloat16 l1 = __float2bfloat16_rn(v.y - __bfloat162float(h1));
    __nv_bfloat16 l2 = __float2bfloat16_rn(v.z - __bfloat162float(h2));
    __nv_bfloat16 l3 = __float2bfloat16_rn(v.w - __bfloat162float(h3));
    ((__nv_bfloat162*)(hi + i))[0] = __halves2bfloat162(h0, h1);
    ((__nv_bfloat162*)(hi + i))[1] = __halves2bfloat162(h2, h3);
    ((__nv_bfloat162*)(lo + i))[0] = __halves2bfloat162(l0, l1);
    ((__nv_bfloat162*)(lo + i))[1] = __halves2bfloat162(l2, l3);
}

// ---------------------------------------------------------------------------
// HMMA GEMM (bf16x3 fused-pass): Y[m,n] = sum_k A[m,k]*B[n,k] + bias[n].
// K-chunk 32; smem rows pack hi (granules 0-3) and lo (granules 4-7) of the
// same 32 k-values -> each global element loaded exactly once. Per k16 slice:
// load ahi/alo/bh/bl fragments, issue all 3 split combos from registers.
// CTA 128x128, 8 warps (64x32 warp tile), 2-stage cp.async, 1 sync/chunk.
// ---------------------------------------------------------------------------
#define GEMM_SMEM (2*32768)   // 2 stages x (A 16KB + B 16KB)

__device__ __forceinline__ void gemm_hmma(
    const __nv_bfloat16* __restrict__ Ahi, const __nv_bfloat16* __restrict__ Alo,
    const __nv_bfloat16* __restrict__ Bhi, const __nv_bfloat16* __restrict__ Blo,
    const float* __restrict__ bias, float* __restrict__ Yf,
    __nv_bfloat16* __restrict__ Yhi, __nv_bfloat16* __restrict__ Ylo)
{
    extern __shared__ char sm[];
    const uint32_t sb = smem_u32(sm);
    const int tid = threadIdx.x;
    const int wid = tid >> 5, lane = tid & 31;
    const int warp_m = (wid >> 2) << 6;     // 0 / 64
    const int warp_n = (wid & 3) << 5;      // 0..96
    const int bm = blockIdx.y * 128, bn = blockIdx.x * 128;
    const int sub = lane >> 3, l7 = lane & 7;

    float acc[4][4][4];
#pragma unroll
    for (int mt = 0; mt < 4; mt++)
#pragma unroll
        for (int nt = 0; nt < 4; nt++)
#pragma unroll
            for (int j = 0; j < 4; j++) acc[mt][nt][j] = 0.f;

    // chunk c (0..31): kt = c*32. Row layout: [k0..31 hi | k0..31 lo] = 128B.
    auto load_chunk = [&](int c, int st) {
        const int kt = c * 32;
        const uint32_t stA = sb + st * 32768;
        const uint32_t stB = stA + 16384;
#pragma unroll
        for (int i = 0; i < 4; i++) {
            int gid = i * 256 + tid;
            int r = gid >> 3, g = gid & 7;
            const __nv_bfloat16* s = (g < 4)
                ? Ahi + (size_t)(bm + r) * DD + kt + g * 8
                : Alo + (size_t)(bm + r) * DD + kt + (g - 4) * 8;
            cpa16(stA + SW(r, g), s);
        }
#pragma unroll
        for (int i = 0; i < 4; i++) {
            int gid = i * 256 + tid;
            int r = gid >> 3, g = gid & 7;
            const __nv_bfloat16* s = (g < 4)
                ? Bhi + (size_t)(bn + r) * DD + kt + g * 8
                : Blo + (size_t)(bn + r) * DD + kt + (g - 4) * 8;
            cpa16(stB + SW(r, g), s);
        }
        CP_COMMIT();
    };

    load_chunk(0, 0);

    for (int c = 0; c < 32; c++) {
        const int st = c & 1;
        CP_WAIT(0);
        __syncthreads();
        if (c < 31) load_chunk(c + 1, st ^ 1);

        const uint32_t stA = sb + st * 32768;
        const uint32_t stB = stA + 16384;
#pragma unroll
        for (int ks = 0; ks < 2; ks++) {
            const int gh = ks * 2 + (sub >> 1);   // hi granule
            const int gl = gh + 4;                // lo granule
            uint32_t ahi[4][4], alo[4][4];
#pragma unroll
            for (int mt = 0; mt < 4; mt++) {
                int row = warp_m + mt * 16 + ((sub & 1) << 3) + l7;
                ldm_x4(ahi[mt], stA + SW(row, gh));
                ldm_x4(alo[mt], stA + SW(row, gl));
            }
#pragma unroll
            for (int hb = 0; hb < 2; hb++) {
                int row = warp_n + hb * 16 + ((sub & 1) << 3) + l7;
                uint32_t bh[4], bl[4];
                ldm_x4(bh, stB + SW(row, gh));
                ldm_x4(bl, stB + SW(row, gl));
#pragma unroll
                for (int mt = 0; mt < 4; mt++) {
                    mma16816(acc[mt][hb*2],   ahi[mt], bh[0], bh[2]);
                    mma16816(acc[mt][hb*2+1], ahi[mt], bh[1], bh[3]);
                    mma16816(acc[mt][hb*2],   ahi[mt], bl[0], bl[2]);
                    mma16816(acc[mt][hb*2+1], ahi[mt], bl[1], bl[3]);
                    mma16816(acc[mt][hb*2],   alo[mt], bh[0], bh[2]);
                    mma16816(acc[mt][hb*2+1], alo[mt], bh[1], bh[3]);
                }
            }
        }
    }

    // Epilogue
    const int rq = lane >> 2, cq = (lane & 3) << 1;
#pragma unroll
    for (int mt = 0; mt < 4; mt++) {
        int row = bm + warp_m + mt * 16 + rq;
#pragma unroll
        for (int nt = 0; nt < 4; nt++) {
            int col = bn + warp_n + nt * 8 + cq;
            float b0 = __ldg(bias + col), b1 = __ldg(bias + col + 1);
            float y00 = acc[mt][nt][0] + b0, y01 = acc[mt][nt][1] + b1;
            float y10 = acc[mt][nt][2] + b0, y11 = acc[mt][nt][3] + b1;
            if (Yf) {
                *(float2*)(Yf + (size_t)row * DD + col)       = make_float2(y00, y01);
                *(float2*)(Yf + (size_t)(row + 8) * DD + col) = make_float2(y10, y11);
            } else {
                __nv_bfloat162 h0 = __floats2bfloat162_rn(y00, y01);
                __nv_bfloat162 h1 = __floats2bfloat162_rn(y10, y11);
                __nv_bfloat162 l0 = __floats2bfloat162_rn(y00 - __bfloat162float(h0.x),
                                                          y01 - __bfloat162float(h0.y));
                __nv_bfloat162 l1 = __floats2bfloat162_rn(y10 - __bfloat162float(h1.x),
                                                          y11 - __bfloat162float(h1.y));
                *(__nv_bfloat162*)(Yhi + (size_t)row * DD + col)       = h0;
                *(__nv_bfloat162*)(Yhi + (size_t)(row + 8) * DD + col) = h1;
                *(__nv_bfloat162*)(Ylo + (size_t)row * DD + col)       = l0;
                *(__nv_bfloat162*)(Ylo + (size_t)(row + 8) * DD + col) = l1;
            }
        }
    }
}

__global__ __launch_bounds__(256, 2) void qkv_hmma_kernel(
    const float* __restrict__ qb, const float* __restrict__ kb,
    const float* __restrict__ vb)
{
    const int z = blockIdx.z;
    if (z == 0)      gemm_hmma(g_xhi, g_xlo, g_whi[0], g_wlo[0], qb, g_q, 0, 0);
    else if (z == 1) gemm_hmma(g_xhi, g_xlo, g_whi[1], g_wlo[1], kb, g_k, 0, 0);
    else             gemm_hmma(g_xhi, g_xlo, g_whi[2], g_wlo[2], vb, 0, g_vhi, g_vlo);
}
__global__ __launch_bounds__(256, 2) void oproj_hmma_kernel(
    const float* __restrict__ ob, float* __restrict__ out)
{
    gemm_hmma(g_ohi, g_olo, g_whi[3], g_wlo[3], ob, out, 0, 0);
}

// ---------------------------------------------------------------------------
// Per-head LayerNorm on Q (x0.125 folded) and K -> bf16 hi/lo.
// ---------------------------------------------------------------------------
__global__ __launch_bounds__(256) void ln_kernel(
    const float* __restrict__ qg, const float* __restrict__ qb,
    const float* __restrict__ kg, const float* __restrict__ kb)
{
    const int warp = threadIdx.x >> 5;
    const int lane = threadIdx.x & 31;
    int row = blockIdx.x * 8 + warp;
    const int NR = BB*SS*HH;

    const float* buf; const float* g; const float* b;
    __nv_bfloat16 *hi, *lo;
    float scale;
    if (row < NR) { buf = g_q; g = qg; b = qb; hi = g_qhi; lo = g_qlo; scale = 0.125f; }
    else { buf = g_k; g = kg; b = kb; hi = g_khi; lo = g_klo; scale = 1.f; row -= NR; }

    const float* p = buf + (size_t)row * HD;
    float x0 = p[lane], x1 = p[lane + 32];

    float s = x0 + x1;
#pragma unroll
    for (int off = 16; off; off >>= 1) s += __shfl_xor_sync(~0u, s, off);
    float mu = s * (1.f / 64.f);

    float d0 = x0 - mu, d1 = x1 - mu;
    float vv = d0*d0 + d1*d1;
#pragma unroll
    for (int off = 16; off; off >>= 1) vv += __shfl_xor_sync(~0u, vv, off);
    float rstd = rsqrtf(vv * (1.f / 64.f) + 1e-5f);

    float y0 = (d0 * rstd * g[lane]      + b[lane])      * scale;
    float y1 = (d1 * rstd * g[lane + 32] + b[lane + 32]) * scale;
    __nv_bfloat16 h0 = __float2bfloat16_rn(y0);
    __nv_bfloat16 h1 = __float2bfloat16_rn(y1);
    size_t off0 = (size_t)row * HD + lane;
    hi[off0]      = h0;
    hi[off0 + 32] = h1;
    lo[off0]      = __float2bfloat16_rn(y0 - __bfloat162float(h0));
    lo[off0 + 32] = __float2bfloat16_rn(y1 - __bfloat162float(h1));
}

// ---------------------------------------------------------------------------
// Flash attention, HMMA bf16x3 fused-pass. 256 threads = 8 warps, q-tile 128.
// K/V hi/lo double-buffered, 1 sync/chunk. P hi/lo conversion is per-kvt
// inside the PV loop (8 temp regs) to avoid R4's register spills.
// Dynamic smem 96KB: Qhi 16K, Qlo 16K, 2 stages x (KH,KL,VH,VL 8K each).
// ---------------------------------------------------------------------------
#define FLASH_SMEM (32768 + 2*32768)

__global__ __launch_bounds__(256, 2) void flash_hmma_kernel()
{
    extern __shared__ char fsm[];
    const uint32_t sb = smem_u32(fsm);
    const uint32_t QH = sb, QL = sb + 16384;

    const int tid = threadIdx.x;
    const int wid = tid >> 5, lane = tid & 31;
    const int sub = lane >> 3, l7 = lane & 7;
    const int rq = lane >> 2, cq = (lane & 3) << 1;
    const int b = blockIdx.z, h = blockIdx.y;
    const int q0 = blockIdx.x * 128;
    const size_t hbase = (size_t)b * SS * DD + (size_t)h * HD;

    // Load Q hi/lo tiles (128 rows) once
#pragma unroll
    for (int i = 0; i < 4; i++) {
        int gid = i * 256 + tid;
        int r = gid >> 3, g = gid & 7;
        size_t src = hbase + (size_t)(q0 + r) * DD + g * 8;
        cpa16(QH + SW(r, g), g_qhi + src);
        cpa16(QL + SW(r, g), g_qlo + src);
    }
    CP_COMMIT();

    const __nv_bfloat16* kvsrc[4] = { g_khi, g_klo, g_vhi, g_vlo };
    auto load_kv = [&](int c0, int st) {
        const uint32_t stage = sb + 32768 + st * 32768;
#pragma unroll
        for (int t = 0; t < 4; t++) {
            const uint32_t dstt = stage + t * 8192;
#pragma unroll
            for (int i = 0; i < 2; i++) {
                int gid = i * 256 + tid;
                int r = gid >> 3, g = gid & 7;
                cpa16(dstt + SW(r, g),
                      kvsrc[t] + hbase + (size_t)(c0 + r) * DD + g * 8);
            }
        }
        CP_COMMIT();
    };

    load_kv(0, 0);

    float o[8][4];
#pragma unroll
    for (int nt = 0; nt < 8; nt++)
#pragma unroll
        for (int j = 0; j < 4; j++) o[nt][j] = 0.f;
    float m0 = -1e30f, m1 = -1e30f, l0 = 0.f, l1 = 0.f;

    for (int cidx = 0; cidx < SS / 64; cidx++) {
        const int st = cidx & 1;
        CP_WAIT(0);
        __syncthreads();
        if (cidx + 1 < SS / 64) load_kv((cidx + 1) * 64, st ^ 1);

        const uint32_t stage = sb + 32768 + st * 32768;
        const uint32_t KH = stage, KL = stage + 8192,
                       VH = stage + 16384, VL = stage + 24576;

        // ---- S = Q' @ K^T : fused 3-pass per k16 slice ----
        float s[8][4];
#pragma unroll
        for (int nt = 0; nt < 8; nt++)
#pragma unroll
            for (int j = 0; j < 4; j++) s[nt][j] = 0.f;

#pragma unroll
        for (int ks = 0; ks < 4; ks++) {
            const int g = ks * 2 + (sub >> 1);
            uint32_t ah[4], al[4];
            {
                int row = wid * 16 + ((sub & 1) << 3) + l7;
                ldm_x4(ah, QH + SW(row, g));
                ldm_x4(al, QL + SW(row, g));
            }
#pragma unroll
            for (int nb = 0; nb < 4; nb++) {
                int row = nb * 16 + ((sub & 1) << 3) + l7;
                uint32_t kh[4], kl[4];
                ldm_x4(kh, KH + SW(row, g));
                ldm_x4(kl, KL + SW(row, g));
                mma16816(s[nb*2],   ah, kh[0], kh[2]);
                mma16816(s[nb*2+1], ah, kh[1], kh[3]);
                mma16816(s[nb*2],   ah, kl[0], kl[2]);
                mma16816(s[nb*2+1], ah, kl[1], kl[3]);
                mma16816(s[nb*2],   al, kh[0], kh[2]);
                mma16816(s[nb*2+1], al, kh[1], kh[3]);
            }
        }

        // ---- online softmax ----
        float rmax0 = -1e30f, rmax1 = -1e30f;
#pragma unroll
        for (int nt = 0; nt < 8; nt++) {
            rmax0 = fmaxf(rmax0, fmaxf(s[nt][0], s[nt][1]));
            rmax1 = fmaxf(rmax1, fmaxf(s[nt][2], s[nt][3]));
        }
        rmax0 = fmaxf(rmax0, __shfl_xor_sync(~0u, rmax0, 1));
        rmax0 = fmaxf(rmax0, __shfl_xor_sync(~0u, rmax0, 2));
        rmax1 = fmaxf(rmax1, __shfl_xor_sync(~0u, rmax1, 1));
        rmax1 = fmaxf(rmax1, __shfl_xor_sync(~0u, rmax1, 2));

        float mn0 = fmaxf(m0, rmax0), mn1 = fmaxf(m1, rmax1);
        float corr0 = __expf(m0 - mn0), corr1 = __expf(m1 - mn1);
        m0 = mn0; m1 = mn1;

        float rs0 = 0.f, rs1 = 0.f;
#pragma unroll
        for (int nt = 0; nt < 8; nt++) {
            s[nt][0] = __expf(s[nt][0] - m0);
            s[nt][1] = __expf(s[nt][1] - m0);
            s[nt][2] = __expf(s[nt][2] - m1);
            s[nt][3] = __expf(s[nt][3] - m1);
            rs0 += s[nt][0] + s[nt][1];
            rs1 += s[nt][2] + s[nt][3];
        }
        rs0 += __shfl_xor_sync(~0u, rs0, 1); rs0 += __shfl_xor_sync(~0u, rs0, 2);
        rs1 += __shfl_xor_sync(~0u, rs1, 1); rs1 += __shfl_xor_sync(~0u, rs1, 2);
        l0 = l0 * corr0 + rs0;
        l1 = l1 * corr1 + rs1;
#pragma unroll
        for (int nt = 0; nt < 8; nt++) {
            o[nt][0] *= corr0; o[nt][1] *= corr0;
            o[nt][2] *= corr1; o[nt][3] *= corr1;
        }

        // ---- O += P @ V : per-kvt in-register P split, fused 3-pass ----
#pragma unroll
        for (int kvt = 0; kvt < 4; kvt++) {
            const float* t0 = s[kvt*2];
            const float* t1 = s[kvt*2+1];
            uint32_t ph[4], pl[4];
            ph[0] = pack_bf(t0[0], t0[1]);
            ph[1] = pack_bf(t0[2], t0[3]);
            ph[2] = pack_bf(t1[0], t1[1]);
            ph[3] = pack_bf(t1[2], t1[3]);
            {
                __nv_bfloat162 h0 = *(__nv_bfloat162*)&ph[0];
                __nv_bfloat162 h1 = *(__nv_bfloat162*)&ph[1];
                __nv_bfloat162 h2 = *(__nv_bfloat162*)&ph[2];
                __nv_bfloat162 h3 = *(__nv_bfloat162*)&ph[3];
                pl[0] = pack_bf(t0[0] - __bfloat162float(h0.x),
                                t0[1] - __bfloat162float(h0.y));
                pl[1] = pack_bf(t0[2] - __bfloat162float(h1.x),
                                t0[3] - __bfloat162float(h1.y));
                pl[2] = pack_bf(t1[0] - __bfloat162float(h2.x),
                                t1[1] - __bfloat162float(h2.y));
                pl[3] = pack_bf(t1[2] - __bfloat162float(h3.x),
                                t1[3] - __bfloat162float(h3.y));
            }
            int row = kvt * 16 + ((sub & 1) << 3) + l7;
#pragma unroll
            for (int db = 0; db < 4; db++) {
                int g = db * 2 + (sub >> 1);
                uint32_t vh[4], vl[4];
                ldm_x4_t(vh, VH + SW(row, g));
                ldm_x4_t(vl, VL + SW(row, g));
                mma16816(o[db*2],   ph, vh[0], vh[1]);
                mma16816(o[db*2+1], ph, vh[2], vh[3]);
                mma16816(o[db*2],   ph, vl[0], vl[1]);
                mma16816(o[db*2+1], ph, vl[2], vl[3]);
                mma16816(o[db*2],   pl, vh[0], vh[1]);
                mma16816(o[db*2+1], pl, vh[2], vh[3]);
            }
        }
    }

    // ---- finalize: divide by l, write bf16 hi/lo split directly ----
    float inv0 = 1.f / l0, inv1 = 1.f / l1;
    int row0 = q0 + wid * 16 + rq;
#pragma unroll
    for (int nt = 0; nt < 8; nt++) {
        int col = nt * 8 + cq;
        float y00 = o[nt][0] * inv0, y01 = o[nt][1] * inv0;
        float y10 = o[nt][2] * inv1, y11 = o[nt][3] * inv1;
        __nv_bfloat162 h0 = __floats2bfloat162_rn(y00, y01);
        __nv_bfloat162 h1 = __floats2bfloat162_rn(y10, y11);
        __nv_bfloat162 lo0 = __floats2bfloat162_rn(y00 - __bfloat162float(h0.x),
                                                   y01 - __bfloat162float(h0.y));
        __nv_bfloat162 lo1 = __floats2bfloat162_rn(y10 - __bfloat162float(h1.x),
                                                   y11 - __bfloat162float(h1.y));
        *(__nv_bfloat162*)(g_ohi + hbase + (size_t)row0 * DD + col)       = h0;
        *(__nv_bfloat162*)(g_ohi + hbase + (size_t)(row0 + 8) * DD + col) = h1;
        *(__nv_bfloat162*)(g_olo + hbase + (size_t)row0 * DD + col)       = lo0;
        *(__nv_bfloat162*)(g_olo + hbase + (size_t)(row0 + 8) * DD + col) = lo1;
    }
}

// ---------------------------------------------------------------------------
extern "C" void kernel_launch(void* const* d_in, const int* in_sizes, int n_in,
                              void* d_out, int out_size)
{
    const float* x   = (const float*)d_in[0];
    const float* qw  = (const float*)d_in[1];
    const float* qb  = (const float*)d_in[2];
    const float* kw  = (const float*)d_in[3];
    const float* kb  = (const float*)d_in[4];
    const float* vw  = (const float*)d_in[5];
    const float* vb  = (const float*)d_in[6];
    const float* ow  = (const float*)d_in[7];
    const float* ob  = (const float*)d_in[8];
    const float* qlg = (const float*)d_in[9];
    const float* qlb = (const float*)d_in[10];
    const float* klg = (const float*)d_in[11];
    const float* klb = (const float*)d_in[12];
    float* out = (float*)d_out;

    cudaFuncSetAttribute(qkv_hmma_kernel,
                         cudaFuncAttributeMaxDynamicSharedMemorySize, GEMM_SMEM);
    cudaFuncSetAttribute(oproj_hmma_kernel,
                         cudaFuncAttributeMaxDynamicSharedMemorySize, GEMM_SMEM);
    cudaFuncSetAttribute(flash_hmma_kernel,
                         cudaFuncAttributeMaxDynamicSharedMemorySize, FLASH_SMEM);

    // fp32 -> bf16 hi/lo splits (X + 4 weights)
    conv_split_kernel<<<NTOK*DD/1024, 256>>>(x,  0);
    conv_split_kernel<<<DD*DD/1024,  256>>>(qw, 2);
    conv_split_kernel<<<DD*DD/1024,  256>>>(kw, 3);
    conv_split_kernel<<<DD*DD/1024,  256>>>(vw, 4);
    conv_split_kernel<<<DD*DD/1024,  256>>>(ow, 5);

    qkv_hmma_kernel<<<dim3(DD/128, NTOK/128, 3), 256, GEMM_SMEM>>>(qb, kb, vb);
    ln_kernel<<<(2 * BB * SS * HH) / 8, 256>>>(qlg, qlb, klg, klb);
    flash_hmma_kernel<<<dim3(SS/128, HH, BB), 256, FLASH_SMEM>>>();
    oproj_hmma_kernel<<<dim3(DD/128, NTOK/128), 256, GEMM_SMEM>>>(ob, out);
}

// round 7
// speedup vs baseline: 1.5670x; 1.4854x over previous
#include <cuda_runtime.h>
#include <cuda_fp16.h>
#include <cstdint>

// Problem constants
#define BB 2
#define SS 2048
#define DD 1024
#define HH 16
#define HD 64
#define NTOK (BB*SS)   // 4096

// ---------------------------------------------------------------------------
// Scratch (__device__ globals per allocation rules).
// ---------------------------------------------------------------------------
__device__ float g_q[NTOK*DD];     // fp32 Q proj (pre-LN)
__device__ float g_k[NTOK*DD];     // fp32 K proj (pre-LN)
__device__ __half g_xh[NTOK*DD];   // X hi
__device__ __half g_xl[NTOK*DD];   // X lo
__device__ __half g_oh[NTOK*DD];   // attn-out hi
__device__ __half g_ol[NTOK*DD];   // attn-out lo
__device__ __half g_vh[NTOK*DD];   // V hi
__device__ __half g_vl[NTOK*DD];   // V lo
__device__ __half g_qh[NTOK*DD];   // LN(Q)*0.125 hi
__device__ __half g_ql[NTOK*DD];   // LN(Q)*0.125 lo
__device__ __half g_kh[NTOK*DD];   // LN(K) single fp16
__device__ __half g_w[4][DD*DD];   // weights single fp16

// ---------------------------------------------------------------------------
// Helpers (sm_80-era instructions only)
// ---------------------------------------------------------------------------
__device__ __forceinline__ uint32_t smem_u32(const void* p) {
    uint32_t a;
    asm("{ .reg .u64 t; cvta.to.shared.u64 t, %1; cvt.u32.u64 %0, t; }"
        : "=r"(a) : "l"(p));
    return a;
}
__device__ __forceinline__ void cpa16(uint32_t dst, const void* src) {
    asm volatile("cp.async.cg.shared.global [%0], [%1], 16;" :: "r"(dst), "l"(src));
}
#define CP_COMMIT() asm volatile("cp.async.commit_group;" ::: "memory")
#define CP_WAIT(n)  asm volatile("cp.async.wait_group %0;" :: "n"(n) : "memory")

__device__ __forceinline__ void ldm_x4(uint32_t* r, uint32_t addr) {
    asm volatile("ldmatrix.sync.aligned.m8n8.x4.shared.b16 {%0,%1,%2,%3}, [%4];"
                 : "=r"(r[0]), "=r"(r[1]), "=r"(r[2]), "=r"(r[3]) : "r"(addr));
}
__device__ __forceinline__ void ldm_x4_t(uint32_t* r, uint32_t addr) {
    asm volatile("ldmatrix.sync.aligned.m8n8.x4.trans.shared.b16 {%0,%1,%2,%3}, [%4];"
                 : "=r"(r[0]), "=r"(r[1]), "=r"(r[2]), "=r"(r[3]) : "r"(addr));
}
__device__ __forceinline__ void mma16816(float* d, const uint32_t* a,
                                         uint32_t b0, uint32_t b1) {
    asm volatile(
        "mma.sync.aligned.m16n8k16.row.col.f32.f16.f16.f32 "
        "{%0,%1,%2,%3}, {%4,%5,%6,%7}, {%8,%9}, {%0,%1,%2,%3};"
        : "+f"(d[0]), "+f"(d[1]), "+f"(d[2]), "+f"(d[3])
        : "r"(a[0]), "r"(a[1]), "r"(a[2]), "r"(a[3]), "r"(b0), "r"(b1));
}
__device__ __forceinline__ uint32_t pack_h2(float lo, float hi) {
    __half2 t = __floats2half2_rn(lo, hi);
    return *(uint32_t*)&t;
}
// swizzled byte offset within a tile of 128B rows, 16B granules g=0..7
#define SW(r, g) ((r)*128 + ((((g) ^ ((r)&7))) << 4))

// ---------------------------------------------------------------------------
// fp32 -> fp16 hi/lo split of X (dst 0), or single-fp16 weight (dst 2..5)
// ---------------------------------------------------------------------------
__global__ __launch_bounds__(256) void conv_kernel(const float* __restrict__ src,
                                                   int dst)
{
    int i = (blockIdx.x * 256 + threadIdx.x) * 4;
    float4 v = *(const float4*)(src + i);
    if (dst == 0) {
        __half h0 = __float2half_rn(v.x), h1 = __float2half_rn(v.y);
        __half h2 = __float2half_rn(v.z), h3 = __float2half_rn(v.w);
        ((__half2*)(g_xh + i))[0] = __halves2half2(h0, h1);
        ((__half2*)(g_xh + i))[1] = __halves2half2(h2, h3);
        ((__half2*)(g_xl + i))[0] = __floats2half2_rn(v.x - __half2float(h0),
                                                      v.y - __half2float(h1));
        ((__half2*)(g_xl + i))[1] = __floats2half2_rn(v.z - __half2float(h2),
                                                      v.w - __half2float(h3));
    } else {
        __half* w = g_w[dst-2];
        ((__half2*)(w + i))[0] = __floats2half2_rn(v.x, v.y);
        ((__half2*)(w + i))[1] = __floats2half2_rn(v.z, v.w);
    }
}

// ---------------------------------------------------------------------------
// HMMA GEMM fp16 2-pass: Y[m,n] = sum_k A[m,k]*B[n,k] + bias[n],
// A = Ah + Al (fp16 split), B single fp16. CTA 128x128, 8 warps (64x32 warp
// tile), K-chunk 64, 2-stage cp.async, 1 sync/chunk.
// Stage: Ah 16KB + Al 16KB + B 16KB = 48KB; 2 stages = 96KB dynamic.
// Epilogue: fp32 (Yf) or fused fp16 hi/lo split (Yhi/Ylo).
// ---------------------------------------------------------------------------
#define GEMM_SMEM (2*49152)

__device__ __forceinline__ void gemm_hmma(
    const __half* __restrict__ Ah, const __half* __restrict__ Al,
    const __half* __restrict__ B,
    const float* __restrict__ bias, float* __restrict__ Yf,
    __half* __restrict__ Yhi, __half* __restrict__ Ylo)
{
    extern __shared__ char sm[];
    const uint32_t sb = smem_u32(sm);
    const int tid = threadIdx.x;
    const int wid = tid >> 5, lane = tid & 31;
    const int warp_m = (wid >> 2) << 6;     // 0 / 64
    const int warp_n = (wid & 3) << 5;      // 0..96
    const int bm = blockIdx.y * 128, bn = blockIdx.x * 128;
    const int sub = lane >> 3, l7 = lane & 7;

    float acc[4][4][4];
#pragma unroll
    for (int mt = 0; mt < 4; mt++)
#pragma unroll
        for (int nt = 0; nt < 4; nt++)
#pragma unroll
            for (int j = 0; j < 4; j++) acc[mt][nt][j] = 0.f;

    // chunk c (0..15): kt = c*64
    auto load_chunk = [&](int c, int st) {
        const int kt = c * 64;
        const uint32_t stAh = sb + st * 49152;
        const uint32_t stAl = stAh + 16384;
        const uint32_t stB  = stAh + 32768;
#pragma unroll
        for (int i = 0; i < 4; i++) {
            int gid = i * 256 + tid;
            int r = gid >> 3, g = gid & 7;
            cpa16(stAh + SW(r, g), Ah + (size_t)(bm + r) * DD + kt + g * 8);
        }
#pragma unroll
        for (int i = 0; i < 4; i++) {
            int gid = i * 256 + tid;
            int r = gid >> 3, g = gid & 7;
            cpa16(stAl + SW(r, g), Al + (size_t)(bm + r) * DD + kt + g * 8);
        }
#pragma unroll
        for (int i = 0; i < 4; i++) {
            int gid = i * 256 + tid;
            int r = gid >> 3, g = gid & 7;
            cpa16(stB + SW(r, g), B + (size_t)(bn + r) * DD + kt + g * 8);
        }
        CP_COMMIT();
    };

    load_chunk(0, 0);

    for (int c = 0; c < 16; c++) {
        const int st = c & 1;
        CP_WAIT(0);
        __syncthreads();
        if (c < 15) load_chunk(c + 1, st ^ 1);

        const uint32_t stAh = sb + st * 49152;
        const uint32_t stAl = stAh + 16384;
        const uint32_t stB  = stAh + 32768;
#pragma unroll
        for (int ks = 0; ks < 4; ks++) {
            const int g = ks * 2 + (sub >> 1);
            uint32_t ah[4][4], al[4][4];
#pragma unroll
            for (int mt = 0; mt < 4; mt++) {
                int row = warp_m + mt * 16 + ((sub & 1) << 3) + l7;
                ldm_x4(ah[mt], stAh + SW(row, g));
                ldm_x4(al[mt], stAl + SW(row, g));
            }
#pragma unroll
            for (int hb = 0; hb < 2; hb++) {
                int row = warp_n + hb * 16 + ((sub & 1) << 3) + l7;
                uint32_t bq[4];
                ldm_x4(bq, stB + SW(row, g));
#pragma unroll
                for (int mt = 0; mt < 4; mt++) {
                    mma16816(acc[mt][hb*2],   ah[mt], bq[0], bq[2]);
                    mma16816(acc[mt][hb*2+1], ah[mt], bq[1], bq[3]);
                    mma16816(acc[mt][hb*2],   al[mt], bq[0], bq[2]);
                    mma16816(acc[mt][hb*2+1], al[mt], bq[1], bq[3]);
                }
            }
        }
    }

    // Epilogue
    const int rq = lane >> 2, cq = (lane & 3) << 1;
#pragma unroll
    for (int mt = 0; mt < 4; mt++) {
        int row = bm + warp_m + mt * 16 + rq;
#pragma unroll
        for (int nt = 0; nt < 4; nt++) {
            int col = bn + warp_n + nt * 8 + cq;
            float b0 = __ldg(bias + col), b1 = __ldg(bias + col + 1);
            float y00 = acc[mt][nt][0] + b0, y01 = acc[mt][nt][1] + b1;
            float y10 = acc[mt][nt][2] + b0, y11 = acc[mt][nt][3] + b1;
            if (Yf) {
                *(float2*)(Yf + (size_t)row * DD + col)       = make_float2(y00, y01);
                *(float2*)(Yf + (size_t)(row + 8) * DD + col) = make_float2(y10, y11);
            } else {
                __half h00 = __float2half_rn(y00), h01 = __float2half_rn(y01);
                __half h10 = __float2half_rn(y10), h11 = __float2half_rn(y11);
                *(__half2*)(Yhi + (size_t)row * DD + col)       = __halves2half2(h00, h01);
                *(__half2*)(Yhi + (size_t)(row + 8) * DD + col) = __halves2half2(h10, h11);
                *(__half2*)(Ylo + (size_t)row * DD + col) =
                    __floats2half2_rn(y00 - __half2float(h00), y01 - __half2float(h01));
                *(__half2*)(Ylo + (size_t)(row + 8) * DD + col) =
                    __floats2half2_rn(y10 - __half2float(h10), y11 - __half2float(h11));
            }
        }
    }
}

__global__ __launch_bounds__(256, 2) void qkv_hmma_kernel(
    const float* __restrict__ qb, const float* __restrict__ kb,
    const float* __restrict__ vb)
{
    const int z = blockIdx.z;
    if (z == 0)      gemm_hmma(g_xh, g_xl, g_w[0], qb, g_q, 0, 0);
    else if (z == 1) gemm_hmma(g_xh, g_xl, g_w[1], kb, g_k, 0, 0);
    else             gemm_hmma(g_xh, g_xl, g_w[2], vb, 0, g_vh, g_vl);
}
__global__ __launch_bounds__(256, 2) void oproj_hmma_kernel(
    const float* __restrict__ ob, float* __restrict__ out)
{
    gemm_hmma(g_oh, g_ol, g_w[3], ob, out, 0, 0);
}

// ---------------------------------------------------------------------------
// Per-head LayerNorm: Q (x0.125 folded) -> fp16 hi/lo; K -> fp16 single.
// ---------------------------------------------------------------------------
__global__ __launch_bounds__(256) void ln_kernel(
    const float* __restrict__ qg, const float* __restrict__ qb,
    const float* __restrict__ kg, const float* __restrict__ kb)
{
    const int warp = threadIdx.x >> 5;
    const int lane = threadIdx.x & 31;
    int row = blockIdx.x * 8 + warp;
    const int NR = BB*SS*HH;

    const bool isQ = (row < NR);
    const float* buf = isQ ? g_q : g_k;
    const float* g   = isQ ? qg : kg;
    const float* b   = isQ ? qb : kb;
    const float scale = isQ ? 0.125f : 1.f;
    if (!isQ) row -= NR;

    const float* p = buf + (size_t)row * HD;
    float x0 = p[lane], x1 = p[lane + 32];

    float s = x0 + x1;
#pragma unroll
    for (int off = 16; off; off >>= 1) s += __shfl_xor_sync(~0u, s, off);
    float mu = s * (1.f / 64.f);

    float d0 = x0 - mu, d1 = x1 - mu;
    float vv = d0*d0 + d1*d1;
#pragma unroll
    for (int off = 16; off; off >>= 1) vv += __shfl_xor_sync(~0u, vv, off);
    float rstd = rsqrtf(vv * (1.f / 64.f) + 1e-5f);

    float y0 = (d0 * rstd * g[lane]      + b[lane])      * scale;
    float y1 = (d1 * rstd * g[lane + 32] + b[lane + 32]) * scale;
    size_t off0 = (size_t)row * HD + lane;
    if (isQ) {
        __half h0 = __float2half_rn(y0), h1 = __float2half_rn(y1);
        g_qh[off0]      = h0;
        g_qh[off0 + 32] = h1;
        g_ql[off0]      = __float2half_rn(y0 - __half2float(h0));
        g_ql[off0 + 32] = __float2half_rn(y1 - __half2float(h1));
    } else {
        g_kh[off0]      = __float2half_rn(y0);
        g_kh[off0 + 32] = __float2half_rn(y1);
    }
}

// ---------------------------------------------------------------------------
// Flash attention, HMMA fp16 2-pass. 256 threads = 8 warps, q-tile 128 rows.
// QK: Q(hi/lo split) x K(single). PV: P(single fp16) x V(hi/lo split).
// K/V double-buffered, 1 sync/chunk.
// Smem: Qh 16K + Ql 16K + 2 stages x (K 8K + Vh 8K + Vl 8K) = 80KB dynamic.
// ---------------------------------------------------------------------------
#define FLASH_SMEM (32768 + 2*24576)

__global__ __launch_bounds__(256, 2) void flash_hmma_kernel()
{
    extern __shared__ char fsm[];
    const uint32_t sb = smem_u32(fsm);
    const uint32_t QH = sb, QL = sb + 16384;

    const int tid = threadIdx.x;
    const int wid = tid >> 5, lane = tid & 31;
    const int sub = lane >> 3, l7 = lane & 7;
    const int rq = lane >> 2, cq = (lane & 3) << 1;
    const int b = blockIdx.z, h = blockIdx.y;
    const int q0 = blockIdx.x * 128;
    const size_t hbase = (size_t)b * SS * DD + (size_t)h * HD;

    // Load Q hi/lo tiles (128 rows) once
#pragma unroll
    for (int i = 0; i < 4; i++) {
        int gid = i * 256 + tid;
        int r = gid >> 3, g = gid & 7;
        size_t src = hbase + (size_t)(q0 + r) * DD + g * 8;
        cpa16(QH + SW(r, g), g_qh + src);
        cpa16(QL + SW(r, g), g_ql + src);
    }
    CP_COMMIT();

    const __half* kvsrc[3] = { g_kh, g_vh, g_vl };
    auto load_kv = [&](int c0, int st) {
        const uint32_t stage = sb + 32768 + st * 24576;
#pragma unroll
        for (int t = 0; t < 3; t++) {
            const uint32_t dstt = stage + t * 8192;
#pragma unroll
            for (int i = 0; i < 2; i++) {
                int gid = i * 256 + tid;
                int r = gid >> 3, g = gid & 7;
                cpa16(dstt + SW(r, g),
                      kvsrc[t] + hbase + (size_t)(c0 + r) * DD + g * 8);
            }
        }
        CP_COMMIT();
    };

    load_kv(0, 0);

    float o[8][4];
#pragma unroll
    for (int nt = 0; nt < 8; nt++)
#pragma unroll
        for (int j = 0; j < 4; j++) o[nt][j] = 0.f;
    float m0 = -1e30f, m1 = -1e30f, l0 = 0.f, l1 = 0.f;

    for (int cidx = 0; cidx < SS / 64; cidx++) {
        const int st = cidx & 1;
        CP_WAIT(0);
        __syncthreads();
        if (cidx + 1 < SS / 64) load_kv((cidx + 1) * 64, st ^ 1);

        const uint32_t stage = sb + 32768 + st * 24576;
        const uint32_t KS = stage, VH = stage + 8192, VL = stage + 16384;

        // ---- S = Q' @ K^T : 2-pass (Qh + Ql) x K ----
        float s[8][4];
#pragma unroll
        for (int nt = 0; nt < 8; nt++)
#pragma unroll
            for (int j = 0; j < 4; j++) s[nt][j] = 0.f;

#pragma unroll
        for (int ks = 0; ks < 4; ks++) {
            const int g = ks * 2 + (sub >> 1);
            uint32_t ah[4], al[4];
            {
                int row = wid * 16 + ((sub & 1) << 3) + l7;
                ldm_x4(ah, QH + SW(row, g));
                ldm_x4(al, QL + SW(row, g));
            }
#pragma unroll
            for (int nb = 0; nb < 4; nb++) {
                int row = nb * 16 + ((sub & 1) << 3) + l7;
                uint32_t kq[4];
                ldm_x4(kq, KS + SW(row, g));
                mma16816(s[nb*2],   ah, kq[0], kq[2]);
                mma16816(s[nb*2+1], ah, kq[1], kq[3]);
                mma16816(s[nb*2],   al, kq[0], kq[2]);
                mma16816(s[nb*2+1], al, kq[1], kq[3]);
            }
        }

        // ---- online softmax ----
        float rmax0 = -1e30f, rmax1 = -1e30f;
#pragma unroll
        for (int nt = 0; nt < 8; nt++) {
            rmax0 = fmaxf(rmax0, fmaxf(s[nt][0], s[nt][1]));
            rmax1 = fmaxf(rmax1, fmaxf(s[nt][2], s[nt][3]));
        }
        rmax0 = fmaxf(rmax0, __shfl_xor_sync(~0u, rmax0, 1));
        rmax0 = fmaxf(rmax0, __shfl_xor_sync(~0u, rmax0, 2));
        rmax1 = fmaxf(rmax1, __shfl_xor_sync(~0u, rmax1, 1));
        rmax1 = fmaxf(rmax1, __shfl_xor_sync(~0u, rmax1, 2));

        float mn0 = fmaxf(m0, rmax0), mn1 = fmaxf(m1, rmax1);
        float corr0 = __expf(m0 - mn0), corr1 = __expf(m1 - mn1);
        m0 = mn0; m1 = mn1;

        float rs0 = 0.f, rs1 = 0.f;
#pragma unroll
        for (int nt = 0; nt < 8; nt++) {
            s[nt][0] = __expf(s[nt][0] - m0);
            s[nt][1] = __expf(s[nt][1] - m0);
            s[nt][2] = __expf(s[nt][2] - m1);
            s[nt][3] = __expf(s[nt][3] - m1);
            rs0 += s[nt][0] + s[nt][1];
            rs1 += s[nt][2] + s[nt][3];
        }
        rs0 += __shfl_xor_sync(~0u, rs0, 1); rs0 += __shfl_xor_sync(~0u, rs0, 2);
        rs1 += __shfl_xor_sync(~0u, rs1, 1); rs1 += __shfl_xor_sync(~0u, rs1, 2);
        l0 = l0 * corr0 + rs0;
        l1 = l1 * corr1 + rs1;
#pragma unroll
        for (int nt = 0; nt < 8; nt++) {
            o[nt][0] *= corr0; o[nt][1] *= corr0;
            o[nt][2] *= corr1; o[nt][3] *= corr1;
        }

        // ---- O += P @ V : P single fp16, V 2-pass (Vh + Vl) ----
#pragma unroll
        for (int kvt = 0; kvt < 4; kvt++) {
            const float* t0 = s[kvt*2];
            const float* t1 = s[kvt*2+1];
            uint32_t ph[4];
            ph[0] = pack_h2(t0[0], t0[1]);
            ph[1] = pack_h2(t0[2], t0[3]);
            ph[2] = pack_h2(t1[0], t1[1]);
            ph[3] = pack_h2(t1[2], t1[3]);
            int row = kvt * 16 + ((sub & 1) << 3) + l7;
#pragma unroll
            for (int db = 0; db < 4; db++) {
                int g = db * 2 + (sub >> 1);
                uint32_t vh[4], vl[4];
                ldm_x4_t(vh, VH + SW(row, g));
                ldm_x4_t(vl, VL + SW(row, g));
                mma16816(o[db*2],   ph, vh[0], vh[1]);
                mma16816(o[db*2+1], ph, vh[2], vh[3]);
                mma16816(o[db*2],   ph, vl[0], vl[1]);
                mma16816(o[db*2+1], ph, vl[2], vl[3]);
            }
        }
    }

    // ---- finalize: divide by l, write fp16 hi/lo split ----
    float inv0 = 1.f / l0, inv1 = 1.f / l1;
    int row0 = q0 + wid * 16 + rq;
#pragma unroll
    for (int nt = 0; nt < 8; nt++) {
        int col = nt * 8 + cq;
        float y00 = o[nt][0] * inv0, y01 = o[nt][1] * inv0;
        float y10 = o[nt][2] * inv1, y11 = o[nt][3] * inv1;
        __half h00 = __float2half_rn(y00), h01 = __float2half_rn(y01);
        __half h10 = __float2half_rn(y10), h11 = __float2half_rn(y11);
        *(__half2*)(g_oh + hbase + (size_t)row0 * DD + col)       = __halves2half2(h00, h01);
        *(__half2*)(g_oh + hbase + (size_t)(row0 + 8) * DD + col) = __halves2half2(h10, h11);
        *(__half2*)(g_ol + hbase + (size_t)row0 * DD + col) =
            __floats2half2_rn(y00 - __half2float(h00), y01 - __half2float(h01));
        *(__half2*)(g_ol + hbase + (size_t)(row0 + 8) * DD + col) =
            __floats2half2_rn(y10 - __half2float(h10), y11 - __half2float(h11));
    }
}

// ---------------------------------------------------------------------------
extern "C" void kernel_launch(void* const* d_in, const int* in_sizes, int n_in,
                              void* d_out, int out_size)
{
    const float* x   = (const float*)d_in[0];
    const float* qw  = (const float*)d_in[1];
    const float* qb  = (const float*)d_in[2];
    const float* kw  = (const float*)d_in[3];
    const float* kb  = (const float*)d_in[4];
    const float* vw  = (const float*)d_in[5];
    const float* vb  = (const float*)d_in[6];
    const float* ow  = (const float*)d_in[7];
    const float* ob  = (const float*)d_in[8];
    const float* qlg = (const float*)d_in[9];
    const float* qlb = (const float*)d_in[10];
    const float* klg = (const float*)d_in[11];
    const float* klb = (const float*)d_in[12];
    float* out = (float*)d_out;

    cudaFuncSetAttribute(qkv_hmma_kernel,
                         cudaFuncAttributeMaxDynamicSharedMemorySize, GEMM_SMEM);
    cudaFuncSetAttribute(oproj_hmma_kernel,
                         cudaFuncAttributeMaxDynamicSharedMemorySize, GEMM_SMEM);
    cudaFuncSetAttribute(flash_hmma_kernel,
                         cudaFuncAttributeMaxDynamicSharedMemorySize, FLASH_SMEM);

    conv_kernel<<<NTOK*DD/1024, 256>>>(x,  0);
    conv_kernel<<<DD*DD/1024,  256>>>(qw, 2);
    conv_kernel<<<DD*DD/1024,  256>>>(kw, 3);
    conv_kernel<<<DD*DD/1024,  256>>>(vw, 4);
    conv_kernel<<<DD*DD/1024,  256>>>(ow, 5);

    qkv_hmma_kernel<<<dim3(DD/128, NTOK/128, 3), 256, GEMM_SMEM>>>(qb, kb, vb);
    ln_kernel<<<(2 * BB * SS * HH) / 8, 256>>>(qlg, qlb, klg, klb);
    flash_hmma_kernel<<<dim3(SS/128, HH, BB), 256, FLASH_SMEM>>>();
    oproj_hmma_kernel<<<dim3(DD/128, NTOK/128), 256, GEMM_SMEM>>>(ob, out);
}

// round 9
// speedup vs baseline: 1.8448x; 1.1773x over previous
#include <cuda_runtime.h>
#include <cuda_fp16.h>
#include <cstdint>

// Problem constants
#define BB 2
#define SS 2048
#define DD 1024
#define HH 16
#define HD 64
#define NTOK (BB*SS)   // 4096

// ---------------------------------------------------------------------------
// Scratch (__device__ globals per allocation rules).
// ---------------------------------------------------------------------------
__device__ float g_q[NTOK*DD];     // fp32 Q proj (pre-LN)
__device__ float g_k[NTOK*DD];     // fp32 K proj (pre-LN)
__device__ __half g_xh[NTOK*DD];   // X hi
__device__ __half g_xl[NTOK*DD];   // X lo
__device__ __half g_oh[NTOK*DD];   // attn-out (single fp16)
__device__ __half g_vh[NTOK*DD];   // V (single fp16)
__device__ __half g_qh[NTOK*DD];   // LN(Q)*0.125 hi
__device__ __half g_ql[NTOK*DD];   // LN(Q)*0.125 lo
__device__ __half g_kh[NTOK*DD];   // LN(K) single fp16
__device__ __half g_w[4][DD*DD];   // weights single fp16

// ---------------------------------------------------------------------------
// Helpers (sm_80-era instructions only)
// ---------------------------------------------------------------------------
__device__ __forceinline__ uint32_t smem_u32(const void* p) {
    uint32_t a;
    asm("{ .reg .u64 t; cvta.to.shared.u64 t, %1; cvt.u32.u64 %0, t; }"
        : "=r"(a) : "l"(p));
    return a;
}
__device__ __forceinline__ void cpa16(uint32_t dst, const void* src) {
    asm volatile("cp.async.cg.shared.global [%0], [%1], 16;" :: "r"(dst), "l"(src));
}
#define CP_COMMIT() asm volatile("cp.async.commit_group;" ::: "memory")
#define CP_WAIT(n)  asm volatile("cp.async.wait_group %0;" :: "n"(n) : "memory")

__device__ __forceinline__ void ldm_x4(uint32_t* r, uint32_t addr) {
    asm volatile("ldmatrix.sync.aligned.m8n8.x4.shared.b16 {%0,%1,%2,%3}, [%4];"
                 : "=r"(r[0]), "=r"(r[1]), "=r"(r[2]), "=r"(r[3]) : "r"(addr));
}
__device__ __forceinline__ void ldm_x4_t(uint32_t* r, uint32_t addr) {
    asm volatile("ldmatrix.sync.aligned.m8n8.x4.trans.shared.b16 {%0,%1,%2,%3}, [%4];"
                 : "=r"(r[0]), "=r"(r[1]), "=r"(r[2]), "=r"(r[3]) : "r"(addr));
}
__device__ __forceinline__ void mma16816(float* d, const uint32_t* a,
                                         uint32_t b0, uint32_t b1) {
    asm volatile(
        "mma.sync.aligned.m16n8k16.row.col.f32.f16.f16.f32 "
        "{%0,%1,%2,%3}, {%4,%5,%6,%7}, {%8,%9}, {%0,%1,%2,%3};"
        : "+f"(d[0]), "+f"(d[1]), "+f"(d[2]), "+f"(d[3])
        : "r"(a[0]), "r"(a[1]), "r"(a[2]), "r"(a[3]), "r"(b0), "r"(b1));
}
__device__ __forceinline__ uint32_t pack_h2(float lo, float hi) {
    __half2 t = __floats2half2_rn(lo, hi);
    return *(uint32_t*)&t;
}
// swizzled byte offset within a tile of 128B rows, 16B granules g=0..7
#define SW(r, g) ((r)*128 + ((((g) ^ ((r)&7))) << 4))

// ---------------------------------------------------------------------------
// Conversions: X -> fp16 hi/lo split; 4 weights -> single fp16 (one launch).
// ---------------------------------------------------------------------------
__global__ __launch_bounds__(256) void conv_x_kernel(const float* __restrict__ src)
{
    int i = (blockIdx.x * 256 + threadIdx.x) * 4;
    float4 v = *(const float4*)(src + i);
    __half h0 = __float2half_rn(v.x), h1 = __float2half_rn(v.y);
    __half h2 = __float2half_rn(v.z), h3 = __float2half_rn(v.w);
    ((__half2*)(g_xh + i))[0] = __halves2half2(h0, h1);
    ((__half2*)(g_xh + i))[1] = __halves2half2(h2, h3);
    ((__half2*)(g_xl + i))[0] = __floats2half2_rn(v.x - __half2float(h0),
                                                  v.y - __half2float(h1));
    ((__half2*)(g_xl + i))[1] = __floats2half2_rn(v.z - __half2float(h2),
                                                  v.w - __half2float(h3));
}

__global__ __launch_bounds__(256) void conv_w_kernel(
    const float* __restrict__ qw, const float* __restrict__ kw,
    const float* __restrict__ vw, const float* __restrict__ ow)
{
    const int z = blockIdx.y;
    const float* src = (z == 0) ? qw : ((z == 1) ? kw : ((z == 2) ? vw : ow));
    __half* w = g_w[z];
    int i = (blockIdx.x * 256 + threadIdx.x) * 4;
    float4 v = *(const float4*)(src + i);
    ((__half2*)(w + i))[0] = __floats2half2_rn(v.x, v.y);
    ((__half2*)(w + i))[1] = __floats2half2_rn(v.z, v.w);
}

// ---------------------------------------------------------------------------
// HMMA GEMM: Y[m,n] = sum_k A[m,k]*B[n,k] + bias[n].
// SPLIT=true : A = Ah + Al (fp16 2-pass). SPLIT=false: A = Ah single (1-pass).
// CTA 128x128, 8 warps (64x32 warp tile), K-chunk 64, 2-stage cp.async,
// 1 sync/chunk. Epilogue: fp32 (Yf) or single fp16 (Yh).
// ---------------------------------------------------------------------------
#define GEMM_SMEM_SPLIT  (2*49152)   // Ah 16K + Al 16K + B 16K per stage
#define GEMM_SMEM_SINGLE (2*32768)   // Ah 16K + B 16K per stage

template <bool SPLIT>
__device__ __forceinline__ void gemm_hmma(
    const __half* __restrict__ Ah, const __half* __restrict__ Al,
    const __half* __restrict__ B,
    const float* __restrict__ bias, float* __restrict__ Yf,
    __half* __restrict__ Yh)
{
    extern __shared__ char sm[];
    const uint32_t sb = smem_u32(sm);
    const int tid = threadIdx.x;
    const int wid = tid >> 5, lane = tid & 31;
    const int warp_m = (wid >> 2) << 6;     // 0 / 64
    const int warp_n = (wid & 3) << 5;      // 0..96
    const int bm = blockIdx.y * 128, bn = blockIdx.x * 128;
    const int sub = lane >> 3, l7 = lane & 7;
    const int STAGE = SPLIT ? 49152 : 32768;
    const int BOFF  = SPLIT ? 32768 : 16384;

    float acc[4][4][4];
#pragma unroll
    for (int mt = 0; mt < 4; mt++)
#pragma unroll
        for (int nt = 0; nt < 4; nt++)
#pragma unroll
            for (int j = 0; j < 4; j++) acc[mt][nt][j] = 0.f;

    auto load_chunk = [&](int c, int st) {
        const int kt = c * 64;
        const uint32_t stAh = sb + st * STAGE;
        const uint32_t stB  = stAh + BOFF;
#pragma unroll
        for (int i = 0; i < 4; i++) {
            int gid = i * 256 + tid;
            int r = gid >> 3, g = gid & 7;
            cpa16(stAh + SW(r, g), Ah + (size_t)(bm + r) * DD + kt + g * 8);
        }
        if (SPLIT) {
            const uint32_t stAl = stAh + 16384;
#pragma unroll
            for (int i = 0; i < 4; i++) {
                int gid = i * 256 + tid;
                int r = gid >> 3, g = gid & 7;
                cpa16(stAl + SW(r, g), Al + (size_t)(bm + r) * DD + kt + g * 8);
            }
        }
#pragma unroll
        for (int i = 0; i < 4; i++) {
            int gid = i * 256 + tid;
            int r = gid >> 3, g = gid & 7;
            cpa16(stB + SW(r, g), B + (size_t)(bn + r) * DD + kt + g * 8);
        }
        CP_COMMIT();
    };

    load_chunk(0, 0);

    for (int c = 0; c < 16; c++) {
        const int st = c & 1;
        CP_WAIT(0);
        __syncthreads();
        if (c < 15) load_chunk(c + 1, st ^ 1);

        const uint32_t stAh = sb + st * STAGE;
        const uint32_t stAl = stAh + 16384;
        const uint32_t stB  = stAh + BOFF;
#pragma unroll
        for (int ks = 0; ks < 4; ks++) {
            const int g = ks * 2 + (sub >> 1);
            uint32_t ah[4][4], al[4][4];
#pragma unroll
            for (int mt = 0; mt < 4; mt++) {
                int row = warp_m + mt * 16 + ((sub & 1) << 3) + l7;
                ldm_x4(ah[mt], stAh + SW(row, g));
                if (SPLIT) ldm_x4(al[mt], stAl + SW(row, g));
            }
#pragma unroll
            for (int hb = 0; hb < 2; hb++) {
                int row = warp_n + hb * 16 + ((sub & 1) << 3) + l7;
                uint32_t bq[4];
                ldm_x4(bq, stB + SW(row, g));
#pragma unroll
                for (int mt = 0; mt < 4; mt++) {
                    mma16816(acc[mt][hb*2],   ah[mt], bq[0], bq[2]);
                    mma16816(acc[mt][hb*2+1], ah[mt], bq[1], bq[3]);
                    if (SPLIT) {
                        mma16816(acc[mt][hb*2],   al[mt], bq[0], bq[2]);
                        mma16816(acc[mt][hb*2+1], al[mt], bq[1], bq[3]);
                    }
                }
            }
        }
    }

    // Epilogue
    const int rq = lane >> 2, cq = (lane & 3) << 1;
#pragma unroll
    for (int mt = 0; mt < 4; mt++) {
        int row = bm + warp_m + mt * 16 + rq;
#pragma unroll
        for (int nt = 0; nt < 4; nt++) {
            int col = bn + warp_n + nt * 8 + cq;
            float b0 = __ldg(bias + col), b1 = __ldg(bias + col + 1);
            float y00 = acc[mt][nt][0] + b0, y01 = acc[mt][nt][1] + b1;
            float y10 = acc[mt][nt][2] + b0, y11 = acc[mt][nt][3] + b1;
            if (Yf) {
                *(float2*)(Yf + (size_t)row * DD + col)       = make_float2(y00, y01);
                *(float2*)(Yf + (size_t)(row + 8) * DD + col) = make_float2(y10, y11);
            } else {
                *(__half2*)(Yh + (size_t)row * DD + col)       = __floats2half2_rn(y00, y01);
                *(__half2*)(Yh + (size_t)(row + 8) * DD + col) = __floats2half2_rn(y10, y11);
            }
        }
    }
}

__global__ __launch_bounds__(256, 2) void qkv_hmma_kernel(
    const float* __restrict__ qb, const float* __restrict__ kb,
    const float* __restrict__ vb)
{
    const int z = blockIdx.z;
    if (z == 0)      gemm_hmma<true>(g_xh, g_xl, g_w[0], qb, g_q, 0);
    else if (z == 1) gemm_hmma<true>(g_xh, g_xl, g_w[1], kb, g_k, 0);
    else             gemm_hmma<true>(g_xh, g_xl, g_w[2], vb, 0, g_vh);
}
__global__ __launch_bounds__(256, 2) void oproj_hmma_kernel(
    const float* __restrict__ ob, float* __restrict__ out)
{
    gemm_hmma<false>(g_oh, 0, g_w[3], ob, out, 0);
}

// ---------------------------------------------------------------------------
// Per-head LayerNorm: Q (x0.125 folded) -> fp16 hi/lo; K -> fp16 single.
// ---------------------------------------------------------------------------
__global__ __launch_bounds__(256) void ln_kernel(
    const float* __restrict__ qg, const float* __restrict__ qb,
    const float* __restrict__ kg, const float* __restrict__ kb)
{
    const int warp = threadIdx.x >> 5;
    const int lane = threadIdx.x & 31;
    int row = blockIdx.x * 8 + warp;
    const int NR = BB*SS*HH;

    const bool isQ = (row < NR);
    const float* buf = isQ ? g_q : g_k;
    const float* g   = isQ ? qg : kg;
    const float* b   = isQ ? qb : kb;
    const float scale = isQ ? 0.125f : 1.f;
    if (!isQ) row -= NR;

    const float* p = buf + (size_t)row * HD;
    float x0 = p[lane], x1 = p[lane + 32];

    float s = x0 + x1;
#pragma unroll
    for (int off = 16; off; off >>= 1) s += __shfl_xor_sync(~0u, s, off);
    float mu = s * (1.f / 64.f);

    float d0 = x0 - mu, d1 = x1 - mu;
    float vv = d0*d0 + d1*d1;
#pragma unroll
    for (int off = 16; off; off >>= 1) vv += __shfl_xor_sync(~0u, vv, off);
    float rstd = rsqrtf(vv * (1.f / 64.f) + 1e-5f);

    float y0 = (d0 * rstd * g[lane]      + b[lane])      * scale;
    float y1 = (d1 * rstd * g[lane + 32] + b[lane + 32]) * scale;
    size_t off0 = (size_t)row * HD + lane;
    if (isQ) {
        __half h0 = __float2half_rn(y0), h1 = __float2half_rn(y1);
        g_qh[off0]      = h0;
        g_qh[off0 + 32] = h1;
        g_ql[off0]      = __float2half_rn(y0 - __half2float(h0));
        g_ql[off0 + 32] = __float2half_rn(y1 - __half2float(h1));
    } else {
        g_kh[off0]      = __float2half_rn(y0);
        g_kh[off0 + 32] = __float2half_rn(y1);
    }
}

// ---------------------------------------------------------------------------
// Flash attention, HMMA fp16. 256 threads = 8 warps, q-tile 128 rows.
// QK: Q(hi/lo split) x K(single), 2-pass. PV: P(single) x V(single), 1-pass.
// K/V double-buffered, 1 sync/chunk. Output single fp16.
// Smem: Qh 16K + Ql 16K + 2 stages x (K 8K + V 8K) = 64KB dynamic.
// ---------------------------------------------------------------------------
#define FLASH_SMEM (32768 + 2*16384)

__global__ __launch_bounds__(256, 2) void flash_hmma_kernel()
{
    extern __shared__ char fsm[];
    const uint32_t sb = smem_u32(fsm);
    const uint32_t QH = sb, QL = sb + 16384;

    const int tid = threadIdx.x;
    const int wid = tid >> 5, lane = tid & 31;
    const int sub = lane >> 3, l7 = lane & 7;
    const int rq = lane >> 2, cq = (lane & 3) << 1;
    const int b = blockIdx.z, h = blockIdx.y;
    const int q0 = blockIdx.x * 128;
    const size_t hbase = (size_t)b * SS * DD + (size_t)h * HD;

    // Load Q hi/lo tiles (128 rows) once
#pragma unroll
    for (int i = 0; i < 4; i++) {
        int gid = i * 256 + tid;
        int r = gid >> 3, g = gid & 7;
        size_t src = hbase + (size_t)(q0 + r) * DD + g * 8;
        cpa16(QH + SW(r, g), g_qh + src);
        cpa16(QL + SW(r, g), g_ql + src);
    }
    CP_COMMIT();

    auto load_kv = [&](int c0, int st) {
        const uint32_t stage = sb + 32768 + st * 16384;
#pragma unroll
        for (int i = 0; i < 2; i++) {
            int gid = i * 256 + tid;
            int r = gid >> 3, g = gid & 7;
            cpa16(stage + SW(r, g),
                  g_kh + hbase + (size_t)(c0 + r) * DD + g * 8);
        }
#pragma unroll
        for (int i = 0; i < 2; i++) {
            int gid = i * 256 + tid;
            int r = gid >> 3, g = gid & 7;
            cpa16(stage + 8192 + SW(r, g),
                  g_vh + hbase + (size_t)(c0 + r) * DD + g * 8);
        }
        CP_COMMIT();
    };

    load_kv(0, 0);

    float o[8][4];
#pragma unroll
    for (int nt = 0; nt < 8; nt++)
#pragma unroll
        for (int j = 0; j < 4; j++) o[nt][j] = 0.f;
    float m0 = -1e30f, m1 = -1e30f, l0 = 0.f, l1 = 0.f;

    for (int cidx = 0; cidx < SS / 64; cidx++) {
        const int st = cidx & 1;
        CP_WAIT(0);
        __syncthreads();
        if (cidx + 1 < SS / 64) load_kv((cidx + 1) * 64, st ^ 1);

        const uint32_t stage = sb + 32768 + st * 16384;
        const uint32_t KS = stage, VS = stage + 8192;

        // ---- S = Q' @ K^T : 2-pass (Qh + Ql) x K ----
        float s[8][4];
#pragma unroll
        for (int nt = 0; nt < 8; nt++)
#pragma unroll
            for (int j = 0; j < 4; j++) s[nt][j] = 0.f;

#pragma unroll
        for (int ks = 0; ks < 4; ks++) {
            const int g = ks * 2 + (sub >> 1);
            uint32_t ah[4], al[4];
            {
                int row = wid * 16 + ((sub & 1) << 3) + l7;
                ldm_x4(ah, QH + SW(row, g));
                ldm_x4(al, QL + SW(row, g));
            }
#pragma unroll
            for (int nb = 0; nb < 4; nb++) {
                int row = nb * 16 + ((sub & 1) << 3) + l7;
                uint32_t kq[4];
                ldm_x4(kq, KS + SW(row, g));
                mma16816(s[nb*2],   ah, kq[0], kq[2]);
                mma16816(s[nb*2+1], ah, kq[1], kq[3]);
                mma16816(s[nb*2],   al, kq[0], kq[2]);
                mma16816(s[nb*2+1], al, kq[1], kq[3]);
            }
        }

        // ---- online softmax ----
        float rmax0 = -1e30f, rmax1 = -1e30f;
#pragma unroll
        for (int nt = 0; nt < 8; nt++) {
            rmax0 = fmaxf(rmax0, fmaxf(s[nt][0], s[nt][1]));
            rmax1 = fmaxf(rmax1, fmaxf(s[nt][2], s[nt][3]));
        }
        rmax0 = fmaxf(rmax0, __shfl_xor_sync(~0u, rmax0, 1));
        rmax0 = fmaxf(rmax0, __shfl_xor_sync(~0u, rmax0, 2));
        rmax1 = fmaxf(rmax1, __shfl_xor_sync(~0u, rmax1, 1));
        rmax1 = fmaxf(rmax1, __shfl_xor_sync(~0u, rmax1, 2));

        float mn0 = fmaxf(m0, rmax0), mn1 = fmaxf(m1, rmax1);
        float corr0 = __expf(m0 - mn0), corr1 = __expf(m1 - mn1);
        m0 = mn0; m1 = mn1;

        float rs0 = 0.f, rs1 = 0.f;
#pragma unroll
        for (int nt = 0; nt < 8; nt++) {
            s[nt][0] = __expf(s[nt][0] - m0);
            s[nt][1] = __expf(s[nt][1] - m0);
            s[nt][2] = __expf(s[nt][2] - m1);
            s[nt][3] = __expf(s[nt][3] - m1);
            rs0 += s[nt][0] + s[nt][1];
            rs1 += s[nt][2] + s[nt][3];
        }
        rs0 += __shfl_xor_sync(~0u, rs0, 1); rs0 += __shfl_xor_sync(~0u, rs0, 2);
        rs1 += __shfl_xor_sync(~0u, rs1, 1); rs1 += __shfl_xor_sync(~0u, rs1, 2);
        l0 = l0 * corr0 + rs0;
        l1 = l1 * corr1 + rs1;
#pragma unroll
        for (int nt = 0; nt < 8; nt++) {
            o[nt][0] *= corr0; o[nt][1] *= corr0;
            o[nt][2] *= corr1; o[nt][3] *= corr1;
        }

        // ---- O += P @ V : single x single, 1-pass ----
#pragma unroll
        for (int kvt = 0; kvt < 4; kvt++) {
            const float* t0 = s[kvt*2];
            const float* t1 = s[kvt*2+1];
            uint32_t ph[4];
            ph[0] = pack_h2(t0[0], t0[1]);
            ph[1] = pack_h2(t0[2], t0[3]);
            ph[2] = pack_h2(t1[0], t1[1]);
            ph[3] = pack_h2(t1[2], t1[3]);
            int row = kvt * 16 + ((sub & 1) << 3) + l7;
#pragma unroll
            for (int db = 0; db < 4; db++) {
                int g = db * 2 + (sub >> 1);
                uint32_t vq[4];
                ldm_x4_t(vq, VS + SW(row, g));
                mma16816(o[db*2],   ph, vq[0], vq[1]);
                mma16816(o[db*2+1], ph, vq[2], vq[3]);
            }
        }
    }

    // ---- finalize: divide by l, write single fp16 ----
    float inv0 = 1.f / l0, inv1 = 1.f / l1;
    int row0 = q0 + wid * 16 + rq;
#pragma unroll
    for (int nt = 0; nt < 8; nt++) {
        int col = nt * 8 + cq;
        *(__half2*)(g_oh + hbase + (size_t)row0 * DD + col) =
            __floats2half2_rn(o[nt][0] * inv0, o[nt][1] * inv0);
        *(__half2*)(g_oh + hbase + (size_t)(row0 + 8) * DD + col) =
            __floats2half2_rn(o[nt][2] * inv1, o[nt][3] * inv1);
    }
}

// ---------------------------------------------------------------------------
extern "C" void kernel_launch(void* const* d_in, const int* in_sizes, int n_in,
                              void* d_out, int out_size)
{
    const float* x   = (const float*)d_in[0];
    const float* qw  = (const float*)d_in[1];
    const float* qb  = (const float*)d_in[2];
    const float* kw  = (const float*)d_in[3];
    const float* kb  = (const float*)d_in[4];
    const float* vw  = (const float*)d_in[5];
    const float* vb  = (const float*)d_in[6];
    const float* ow  = (const float*)d_in[7];
    const float* ob  = (const float*)d_in[8];
    const float* qlg = (const float*)d_in[9];
    const float* qlb = (const float*)d_in[10];
    const float* klg = (const float*)d_in[11];
    const float* klb = (const float*)d_in[12];
    float* out = (float*)d_out;

    cudaFuncSetAttribute(qkv_hmma_kernel,
                         cudaFuncAttributeMaxDynamicSharedMemorySize, GEMM_SMEM_SPLIT);
    cudaFuncSetAttribute(oproj_hmma_kernel,
                         cudaFuncAttributeMaxDynamicSharedMemorySize, GEMM_SMEM_SINGLE);
    cudaFuncSetAttribute(flash_hmma_kernel,
                         cudaFuncAttributeMaxDynamicSharedMemorySize, FLASH_SMEM);

    conv_x_kernel<<<NTOK*DD/1024, 256>>>(x);
    conv_w_kernel<<<dim3(DD*DD/1024, 4), 256>>>(qw, kw, vw, ow);

    qkv_hmma_kernel<<<dim3(DD/128, NTOK/128, 3), 256, GEMM_SMEM_SPLIT>>>(qb, kb, vb);
    ln_kernel<<<(2 * BB * SS * HH) / 8, 256>>>(qlg, qlb, klg, klb);
    flash_hmma_kernel<<<dim3(SS/128, HH, BB), 256, FLASH_SMEM>>>();
    oproj_hmma_kernel<<<dim3(DD/128, NTOK/128), 256, GEMM_SMEM_SINGLE>>>(ob, out);
}

// round 10
// speedup vs baseline: 2.0346x; 1.1029x over previous
#include <cuda_runtime.h>
#include <cuda_fp16.h>
#include <cstdint>

// Problem constants
#define BB 2
#define SS 2048
#define DD 1024
#define HH 16
#define HD 64
#define NTOK (BB*SS)   // 4096

// ---------------------------------------------------------------------------
// Scratch (__device__ globals per allocation rules).
// ---------------------------------------------------------------------------
__device__ float g_q[NTOK*DD];     // fp32 Q proj (pre-LN)
__device__ float g_k[NTOK*DD];     // fp32 K proj (pre-LN)
__device__ __half g_xh[NTOK*DD];   // X hi
__device__ __half g_xl[NTOK*DD];   // X lo
__device__ __half g_oh[NTOK*DD];   // attn-out (single fp16)
__device__ __half g_vh[NTOK*DD];   // V (single fp16)
__device__ __half g_qh[NTOK*DD];   // LN(Q)*0.125 single fp16
__device__ __half g_kh[NTOK*DD];   // LN(K) single fp16
__device__ __half g_w[4][DD*DD];   // weights single fp16

// ---------------------------------------------------------------------------
// Helpers (sm_80-era instructions only)
// ---------------------------------------------------------------------------
__device__ __forceinline__ uint32_t smem_u32(const void* p) {
    uint32_t a;
    asm("{ .reg .u64 t; cvta.to.shared.u64 t, %1; cvt.u32.u64 %0, t; }"
        : "=r"(a) : "l"(p));
    return a;
}
__device__ __forceinline__ void cpa16(uint32_t dst, const void* src) {
    asm volatile("cp.async.cg.shared.global [%0], [%1], 16;" :: "r"(dst), "l"(src));
}
#define CP_COMMIT() asm volatile("cp.async.commit_group;" ::: "memory")
#define CP_WAIT(n)  asm volatile("cp.async.wait_group %0;" :: "n"(n) : "memory")

__device__ __forceinline__ void ldm_x4(uint32_t* r, uint32_t addr) {
    asm volatile("ldmatrix.sync.aligned.m8n8.x4.shared.b16 {%0,%1,%2,%3}, [%4];"
                 : "=r"(r[0]), "=r"(r[1]), "=r"(r[2]), "=r"(r[3]) : "r"(addr));
}
__device__ __forceinline__ void ldm_x4_t(uint32_t* r, uint32_t addr) {
    asm volatile("ldmatrix.sync.aligned.m8n8.x4.trans.shared.b16 {%0,%1,%2,%3}, [%4];"
                 : "=r"(r[0]), "=r"(r[1]), "=r"(r[2]), "=r"(r[3]) : "r"(addr));
}
__device__ __forceinline__ void mma16816(float* d, const uint32_t* a,
                                         uint32_t b0, uint32_t b1) {
    asm volatile(
        "mma.sync.aligned.m16n8k16.row.col.f32.f16.f16.f32 "
        "{%0,%1,%2,%3}, {%4,%5,%6,%7}, {%8,%9}, {%0,%1,%2,%3};"
        : "+f"(d[0]), "+f"(d[1]), "+f"(d[2]), "+f"(d[3])
        : "r"(a[0]), "r"(a[1]), "r"(a[2]), "r"(a[3]), "r"(b0), "r"(b1));
}
__device__ __forceinline__ uint32_t pack_h2(float lo, float hi) {
    __half2 t = __floats2half2_rn(lo, hi);
    return *(uint32_t*)&t;
}
// swizzled byte offset within a tile of 128B rows, 16B granules g=0..7
#define SW(r, g) ((r)*128 + ((((g) ^ ((r)&7))) << 4))

// ---------------------------------------------------------------------------
// Conversions: X -> fp16 hi/lo split; 4 weights -> single fp16 (one launch).
// ---------------------------------------------------------------------------
__global__ __launch_bounds__(256) void conv_x_kernel(const float* __restrict__ src)
{
    int i = (blockIdx.x * 256 + threadIdx.x) * 4;
    float4 v = *(const float4*)(src + i);
    __half h0 = __float2half_rn(v.x), h1 = __float2half_rn(v.y);
    __half h2 = __float2half_rn(v.z), h3 = __float2half_rn(v.w);
    ((__half2*)(g_xh + i))[0] = __halves2half2(h0, h1);
    ((__half2*)(g_xh + i))[1] = __halves2half2(h2, h3);
    ((__half2*)(g_xl + i))[0] = __floats2half2_rn(v.x - __half2float(h0),
                                                  v.y - __half2float(h1));
    ((__half2*)(g_xl + i))[1] = __floats2half2_rn(v.z - __half2float(h2),
                                                  v.w - __half2float(h3));
}

__global__ __launch_bounds__(256) void conv_w_kernel(
    const float* __restrict__ qw, const float* __restrict__ kw,
    const float* __restrict__ vw, const float* __restrict__ ow)
{
    const int z = blockIdx.y;
    const float* src = (z == 0) ? qw : ((z == 1) ? kw : ((z == 2) ? vw : ow));
    __half* w = g_w[z];
    int i = (blockIdx.x * 256 + threadIdx.x) * 4;
    float4 v = *(const float4*)(src + i);
    ((__half2*)(w + i))[0] = __floats2half2_rn(v.x, v.y);
    ((__half2*)(w + i))[1] = __floats2half2_rn(v.z, v.w);
}

// ---------------------------------------------------------------------------
// HMMA GEMM: Y[m,n] = sum_k A[m,k]*B[n,k] + bias[n].
// SPLIT=true : A = Ah + Al (fp16 2-pass). SPLIT=false: A = Ah single (1-pass).
// CTA 128x128, 8 warps (64x32 warp tile), K-chunk 64, 2-stage cp.async,
// 1 sync/chunk. Epilogue: fp32 (Yf) or single fp16 (Yh).
// ---------------------------------------------------------------------------
#define GEMM_SMEM_SPLIT  (2*49152)   // Ah 16K + Al 16K + B 16K per stage
#define GEMM_SMEM_SINGLE (2*32768)   // Ah 16K + B 16K per stage

template <bool SPLIT>
__device__ __forceinline__ void gemm_hmma(
    const __half* __restrict__ Ah, const __half* __restrict__ Al,
    const __half* __restrict__ B,
    const float* __restrict__ bias, float* __restrict__ Yf,
    __half* __restrict__ Yh)
{
    extern __shared__ char sm[];
    const uint32_t sb = smem_u32(sm);
    const int tid = threadIdx.x;
    const int wid = tid >> 5, lane = tid & 31;
    const int warp_m = (wid >> 2) << 6;     // 0 / 64
    const int warp_n = (wid & 3) << 5;      // 0..96
    const int bm = blockIdx.y * 128, bn = blockIdx.x * 128;
    const int sub = lane >> 3, l7 = lane & 7;
    const int STAGE = SPLIT ? 49152 : 32768;
    const int BOFF  = SPLIT ? 32768 : 16384;

    float acc[4][4][4];
#pragma unroll
    for (int mt = 0; mt < 4; mt++)
#pragma unroll
        for (int nt = 0; nt < 4; nt++)
#pragma unroll
            for (int j = 0; j < 4; j++) acc[mt][nt][j] = 0.f;

    auto load_chunk = [&](int c, int st) {
        const int kt = c * 64;
        const uint32_t stAh = sb + st * STAGE;
        const uint32_t stB  = stAh + BOFF;
#pragma unroll
        for (int i = 0; i < 4; i++) {
            int gid = i * 256 + tid;
            int r = gid >> 3, g = gid & 7;
            cpa16(stAh + SW(r, g), Ah + (size_t)(bm + r) * DD + kt + g * 8);
        }
        if (SPLIT) {
            const uint32_t stAl = stAh + 16384;
#pragma unroll
            for (int i = 0; i < 4; i++) {
                int gid = i * 256 + tid;
                int r = gid >> 3, g = gid & 7;
                cpa16(stAl + SW(r, g), Al + (size_t)(bm + r) * DD + kt + g * 8);
            }
        }
#pragma unroll
        for (int i = 0; i < 4; i++) {
            int gid = i * 256 + tid;
            int r = gid >> 3, g = gid & 7;
            cpa16(stB + SW(r, g), B + (size_t)(bn + r) * DD + kt + g * 8);
        }
        CP_COMMIT();
    };

    load_chunk(0, 0);

    for (int c = 0; c < 16; c++) {
        const int st = c & 1;
        CP_WAIT(0);
        __syncthreads();
        if (c < 15) load_chunk(c + 1, st ^ 1);

        const uint32_t stAh = sb + st * STAGE;
        const uint32_t stAl = stAh + 16384;
        const uint32_t stB  = stAh + BOFF;
#pragma unroll
        for (int ks = 0; ks < 4; ks++) {
            const int g = ks * 2 + (sub >> 1);
            uint32_t ah[4][4], al[4][4];
#pragma unroll
            for (int mt = 0; mt < 4; mt++) {
                int row = warp_m + mt * 16 + ((sub & 1) << 3) + l7;
                ldm_x4(ah[mt], stAh + SW(row, g));
                if (SPLIT) ldm_x4(al[mt], stAl + SW(row, g));
            }
#pragma unroll
            for (int hb = 0; hb < 2; hb++) {
                int row = warp_n + hb * 16 + ((sub & 1) << 3) + l7;
                uint32_t bq[4];
                ldm_x4(bq, stB + SW(row, g));
#pragma unroll
                for (int mt = 0; mt < 4; mt++) {
                    mma16816(acc[mt][hb*2],   ah[mt], bq[0], bq[2]);
                    mma16816(acc[mt][hb*2+1], ah[mt], bq[1], bq[3]);
                    if (SPLIT) {
                        mma16816(acc[mt][hb*2],   al[mt], bq[0], bq[2]);
                        mma16816(acc[mt][hb*2+1], al[mt], bq[1], bq[3]);
                    }
                }
            }
        }
    }

    // Epilogue
    const int rq = lane >> 2, cq = (lane & 3) << 1;
#pragma unroll
    for (int mt = 0; mt < 4; mt++) {
        int row = bm + warp_m + mt * 16 + rq;
#pragma unroll
        for (int nt = 0; nt < 4; nt++) {
            int col = bn + warp_n + nt * 8 + cq;
            float b0 = __ldg(bias + col), b1 = __ldg(bias + col + 1);
            float y00 = acc[mt][nt][0] + b0, y01 = acc[mt][nt][1] + b1;
            float y10 = acc[mt][nt][2] + b0, y11 = acc[mt][nt][3] + b1;
            if (Yf) {
                *(float2*)(Yf + (size_t)row * DD + col)       = make_float2(y00, y01);
                *(float2*)(Yf + (size_t)(row + 8) * DD + col) = make_float2(y10, y11);
            } else {
                *(__half2*)(Yh + (size_t)row * DD + col)       = __floats2half2_rn(y00, y01);
                *(__half2*)(Yh + (size_t)(row + 8) * DD + col) = __floats2half2_rn(y10, y11);
            }
        }
    }
}

__global__ __launch_bounds__(256, 2) void qkv_hmma_kernel(
    const float* __restrict__ qb, const float* __restrict__ kb,
    const float* __restrict__ vb)
{
    const int z = blockIdx.z;
    if (z == 0)      gemm_hmma<true>(g_xh, g_xl, g_w[0], qb, g_q, 0);
    else if (z == 1) gemm_hmma<true>(g_xh, g_xl, g_w[1], kb, g_k, 0);
    else             gemm_hmma<true>(g_xh, g_xl, g_w[2], vb, 0, g_vh);
}
__global__ __launch_bounds__(256, 2) void oproj_hmma_kernel(
    const float* __restrict__ ob, float* __restrict__ out)
{
    gemm_hmma<false>(g_oh, 0, g_w[3], ob, out, 0);
}

// ---------------------------------------------------------------------------
// Per-head LayerNorm: Q (x0.125 folded) and K, both -> single fp16.
// ---------------------------------------------------------------------------
__global__ __launch_bounds__(256) void ln_kernel(
    const float* __restrict__ qg, const float* __restrict__ qb,
    const float* __restrict__ kg, const float* __restrict__ kb)
{
    const int warp = threadIdx.x >> 5;
    const int lane = threadIdx.x & 31;
    int row = blockIdx.x * 8 + warp;
    const int NR = BB*SS*HH;

    const bool isQ = (row < NR);
    const float* buf = isQ ? g_q : g_k;
    const float* g   = isQ ? qg : kg;
    const float* b   = isQ ? qb : kb;
    __half* dst      = isQ ? g_qh : g_kh;
    const float scale = isQ ? 0.125f : 1.f;
    if (!isQ) row -= NR;

    const float* p = buf + (size_t)row * HD;
    float x0 = p[lane], x1 = p[lane + 32];

    float s = x0 + x1;
#pragma unroll
    for (int off = 16; off; off >>= 1) s += __shfl_xor_sync(~0u, s, off);
    float mu = s * (1.f / 64.f);

    float d0 = x0 - mu, d1 = x1 - mu;
    float vv = d0*d0 + d1*d1;
#pragma unroll
    for (int off = 16; off; off >>= 1) vv += __shfl_xor_sync(~0u, vv, off);
    float rstd = rsqrtf(vv * (1.f / 64.f) + 1e-5f);

    float y0 = (d0 * rstd * g[lane]      + b[lane])      * scale;
    float y1 = (d1 * rstd * g[lane + 32] + b[lane + 32]) * scale;
    size_t off0 = (size_t)row * HD + lane;
    dst[off0]      = __float2half_rn(y0);
    dst[off0 + 32] = __float2half_rn(y1);
}

// ---------------------------------------------------------------------------
// Flash attention, HMMA fp16, all single-pass. 256 threads = 8 warps,
// q-tile 128 rows. QK: Q x K single. PV: P x V single.
// K/V double-buffered, 1 sync/chunk. Output single fp16.
// Smem: Qh 16K + 2 stages x (K 8K + V 8K) = 48KB dynamic.
// ---------------------------------------------------------------------------
#define FLASH_SMEM (16384 + 2*16384)

__global__ __launch_bounds__(256, 2) void flash_hmma_kernel()
{
    extern __shared__ char fsm[];
    const uint32_t sb = smem_u32(fsm);
    const uint32_t QH = sb;

    const int tid = threadIdx.x;
    const int wid = tid >> 5, lane = tid & 31;
    const int sub = lane >> 3, l7 = lane & 7;
    const int rq = lane >> 2, cq = (lane & 3) << 1;
    const int b = blockIdx.z, h = blockIdx.y;
    const int q0 = blockIdx.x * 128;
    const size_t hbase = (size_t)b * SS * DD + (size_t)h * HD;

    // Load Q tile (128 rows) once
#pragma unroll
    for (int i = 0; i < 4; i++) {
        int gid = i * 256 + tid;
        int r = gid >> 3, g = gid & 7;
        cpa16(QH + SW(r, g), g_qh + hbase + (size_t)(q0 + r) * DD + g * 8);
    }
    CP_COMMIT();

    auto load_kv = [&](int c0, int st) {
        const uint32_t stage = sb + 16384 + st * 16384;
#pragma unroll
        for (int i = 0; i < 2; i++) {
            int gid = i * 256 + tid;
            int r = gid >> 3, g = gid & 7;
            cpa16(stage + SW(r, g),
                  g_kh + hbase + (size_t)(c0 + r) * DD + g * 8);
        }
#pragma unroll
        for (int i = 0; i < 2; i++) {
            int gid = i * 256 + tid;
            int r = gid >> 3, g = gid & 7;
            cpa16(stage + 8192 + SW(r, g),
                  g_vh + hbase + (size_t)(c0 + r) * DD + g * 8);
        }
        CP_COMMIT();
    };

    load_kv(0, 0);

    float o[8][4];
#pragma unroll
    for (int nt = 0; nt < 8; nt++)
#pragma unroll
        for (int j = 0; j < 4; j++) o[nt][j] = 0.f;
    float m0 = -1e30f, m1 = -1e30f, l0 = 0.f, l1 = 0.f;

    for (int cidx = 0; cidx < SS / 64; cidx++) {
        const int st = cidx & 1;
        CP_WAIT(0);
        __syncthreads();
        if (cidx + 1 < SS / 64) load_kv((cidx + 1) * 64, st ^ 1);

        const uint32_t stage = sb + 16384 + st * 16384;
        const uint32_t KS = stage, VS = stage + 8192;

        // ---- S = Q @ K^T : single-pass ----
        float s[8][4];
#pragma unroll
        for (int nt = 0; nt < 8; nt++)
#pragma unroll
            for (int j = 0; j < 4; j++) s[nt][j] = 0.f;

#pragma unroll
        for (int ks = 0; ks < 4; ks++) {
            const int g = ks * 2 + (sub >> 1);
            uint32_t ah[4];
            {
                int row = wid * 16 + ((sub & 1) << 3) + l7;
                ldm_x4(ah, QH + SW(row, g));
            }
#pragma unroll
            for (int nb = 0; nb < 4; nb++) {
                int row = nb * 16 + ((sub & 1) << 3) + l7;
                uint32_t kq[4];
                ldm_x4(kq, KS + SW(row, g));
                mma16816(s[nb*2],   ah, kq[0], kq[2]);
                mma16816(s[nb*2+1], ah, kq[1], kq[3]);
            }
        }

        // ---- online softmax ----
        float rmax0 = -1e30f, rmax1 = -1e30f;
#pragma unroll
        for (int nt = 0; nt < 8; nt++) {
            rmax0 = fmaxf(rmax0, fmaxf(s[nt][0], s[nt][1]));
            rmax1 = fmaxf(rmax1, fmaxf(s[nt][2], s[nt][3]));
        }
        rmax0 = fmaxf(rmax0, __shfl_xor_sync(~0u, rmax0, 1));
        rmax0 = fmaxf(rmax0, __shfl_xor_sync(~0u, rmax0, 2));
        rmax1 = fmaxf(rmax1, __shfl_xor_sync(~0u, rmax1, 1));
        rmax1 = fmaxf(rmax1, __shfl_xor_sync(~0u, rmax1, 2));

        float mn0 = fmaxf(m0, rmax0), mn1 = fmaxf(m1, rmax1);
        float corr0 = __expf(m0 - mn0), corr1 = __expf(m1 - mn1);
        m0 = mn0; m1 = mn1;

        float rs0 = 0.f, rs1 = 0.f;
#pragma unroll
        for (int nt = 0; nt < 8; nt++) {
            s[nt][0] = __expf(s[nt][0] - m0);
            s[nt][1] = __expf(s[nt][1] - m0);
            s[nt][2] = __expf(s[nt][2] - m1);
            s[nt][3] = __expf(s[nt][3] - m1);
            rs0 += s[nt][0] + s[nt][1];
            rs1 += s[nt][2] + s[nt][3];
        }
        rs0 += __shfl_xor_sync(~0u, rs0, 1); rs0 += __shfl_xor_sync(~0u, rs0, 2);
        rs1 += __shfl_xor_sync(~0u, rs1, 1); rs1 += __shfl_xor_sync(~0u, rs1, 2);
        l0 = l0 * corr0 + rs0;
        l1 = l1 * corr1 + rs1;
#pragma unroll
        for (int nt = 0; nt < 8; nt++) {
            o[nt][0] *= corr0; o[nt][1] *= corr0;
            o[nt][2] *= corr1; o[nt][3] *= corr1;
        }

        // ---- O += P @ V : single x single ----
#pragma unroll
        for (int kvt = 0; kvt < 4; kvt++) {
            const float* t0 = s[kvt*2];
            const float* t1 = s[kvt*2+1];
            uint32_t ph[4];
            ph[0] = pack_h2(t0[0], t0[1]);
            ph[1] = pack_h2(t0[2], t0[3]);
            ph[2] = pack_h2(t1[0], t1[1]);
            ph[3] = pack_h2(t1[2], t1[3]);
            int row = kvt * 16 + ((sub & 1) << 3) + l7;
#pragma unroll
            for (int db = 0; db < 4; db++) {
                int g = db * 2 + (sub >> 1);
                uint32_t vq[4];
                ldm_x4_t(vq, VS + SW(row, g));
                mma16816(o[db*2],   ph, vq[0], vq[1]);
                mma16816(o[db*2+1], ph, vq[2], vq[3]);
            }
        }
    }

    // ---- finalize: divide by l, write single fp16 ----
    float inv0 = 1.f / l0, inv1 = 1.f / l1;
    int row0 = q0 + wid * 16 + rq;
#pragma unroll
    for (int nt = 0; nt < 8; nt++) {
        int col = nt * 8 + cq;
        *(__half2*)(g_oh + hbase + (size_t)row0 * DD + col) =
            __floats2half2_rn(o[nt][0] * inv0, o[nt][1] * inv0);
        *(__half2*)(g_oh + hbase + (size_t)(row0 + 8) * DD + col) =
            __floats2half2_rn(o[nt][2] * inv1, o[nt][3] * inv1);
    }
}

// ---------------------------------------------------------------------------
extern "C" void kernel_launch(void* const* d_in, const int* in_sizes, int n_in,
                              void* d_out, int out_size)
{
    const float* x   = (const float*)d_in[0];
    const float* qw  = (const float*)d_in[1];
    const float* qb  = (const float*)d_in[2];
    const float* kw  = (const float*)d_in[3];
    const float* kb  = (const float*)d_in[4];
    const float* vw  = (const float*)d_in[5];
    const float* vb  = (const float*)d_in[6];
    const float* ow  = (const float*)d_in[7];
    const float* ob  = (const float*)d_in[8];
    const float* qlg = (const float*)d_in[9];
    const float* qlb = (const float*)d_in[10];
    const float* klg = (const float*)d_in[11];
    const float* klb = (const float*)d_in[12];
    float* out = (float*)d_out;

    cudaFuncSetAttribute(qkv_hmma_kernel,
                         cudaFuncAttributeMaxDynamicSharedMemorySize, GEMM_SMEM_SPLIT);
    cudaFuncSetAttribute(oproj_hmma_kernel,
                         cudaFuncAttributeMaxDynamicSharedMemorySize, GEMM_SMEM_SINGLE);
    cudaFuncSetAttribute(flash_hmma_kernel,
                         cudaFuncAttributeMaxDynamicSharedMemorySize, FLASH_SMEM);

    conv_x_kernel<<<NTOK*DD/1024, 256>>>(x);
    conv_w_kernel<<<dim3(DD*DD/1024, 4), 256>>>(qw, kw, vw, ow);

    qkv_hmma_kernel<<<dim3(DD/128, NTOK/128, 3), 256, GEMM_SMEM_SPLIT>>>(qb, kb, vb);
    ln_kernel<<<(2 * BB * SS * HH) / 8, 256>>>(qlg, qlb, klg, klb);
    flash_hmma_kernel<<<dim3(SS/128, HH, BB), 256, FLASH_SMEM>>>();
    oproj_hmma_kernel<<<dim3(DD/128, NTOK/128), 256, GEMM_SMEM_SINGLE>>>(ob, out);
}

// round 11
// speedup vs baseline: 2.6006x; 1.2782x over previous
#include <cuda_runtime.h>
#include <cuda_fp16.h>
#include <cstdint>

// Problem constants
#define BB 2
#define SS 2048
#define DD 1024
#define HH 16
#define HD 64
#define NTOK (BB*SS)   // 4096

// ---------------------------------------------------------------------------
// Scratch (__device__ globals per allocation rules).
// ---------------------------------------------------------------------------
__device__ float g_q[NTOK*DD];     // fp32 Q proj (pre-LN)
__device__ float g_k[NTOK*DD];     // fp32 K proj (pre-LN)
__device__ __half g_xh[NTOK*DD];   // X (single fp16)
__device__ __half g_oh[NTOK*DD];   // attn-out (single fp16)
__device__ __half g_vh[NTOK*DD];   // V (single fp16)
__device__ __half g_qh[NTOK*DD];   // LN(Q)*0.125 single fp16
__device__ __half g_kh[NTOK*DD];   // LN(K) single fp16
__device__ __half g_w[4][DD*DD];   // weights single fp16

// ---------------------------------------------------------------------------
// Helpers (sm_80-era instructions only)
// ---------------------------------------------------------------------------
__device__ __forceinline__ uint32_t smem_u32(const void* p) {
    uint32_t a;
    asm("{ .reg .u64 t; cvta.to.shared.u64 t, %1; cvt.u32.u64 %0, t; }"
        : "=r"(a) : "l"(p));
    return a;
}
__device__ __forceinline__ void cpa16(uint32_t dst, const void* src) {
    asm volatile("cp.async.cg.shared.global [%0], [%1], 16;" :: "r"(dst), "l"(src));
}
#define CP_COMMIT() asm volatile("cp.async.commit_group;" ::: "memory")
#define CP_WAIT(n)  asm volatile("cp.async.wait_group %0;" :: "n"(n) : "memory")

__device__ __forceinline__ void ldm_x4(uint32_t* r, uint32_t addr) {
    asm volatile("ldmatrix.sync.aligned.m8n8.x4.shared.b16 {%0,%1,%2,%3}, [%4];"
                 : "=r"(r[0]), "=r"(r[1]), "=r"(r[2]), "=r"(r[3]) : "r"(addr));
}
__device__ __forceinline__ void ldm_x4_t(uint32_t* r, uint32_t addr) {
    asm volatile("ldmatrix.sync.aligned.m8n8.x4.trans.shared.b16 {%0,%1,%2,%3}, [%4];"
                 : "=r"(r[0]), "=r"(r[1]), "=r"(r[2]), "=r"(r[3]) : "r"(addr));
}
__device__ __forceinline__ void mma16816(float* d, const uint32_t* a,
                                         uint32_t b0, uint32_t b1) {
    asm volatile(
        "mma.sync.aligned.m16n8k16.row.col.f32.f16.f16.f32 "
        "{%0,%1,%2,%3}, {%4,%5,%6,%7}, {%8,%9}, {%0,%1,%2,%3};"
        : "+f"(d[0]), "+f"(d[1]), "+f"(d[2]), "+f"(d[3])
        : "r"(a[0]), "r"(a[1]), "r"(a[2]), "r"(a[3]), "r"(b0), "r"(b1));
}
__device__ __forceinline__ uint32_t pack_h2(float lo, float hi) {
    __half2 t = __floats2half2_rn(lo, hi);
    return *(uint32_t*)&t;
}
// swizzled byte offset within a tile of 128B rows, 16B granules g=0..7
#define SW(r, g) ((r)*128 + ((((g) ^ ((r)&7))) << 4))

// ---------------------------------------------------------------------------
// Unified fp32 -> fp16 conversion: slab z = 0..3 weights, 4..7 X quarters.
// Each slab = 1M elements; 1024 blocks x 256 threads x 4 elems.
// ---------------------------------------------------------------------------
__global__ __launch_bounds__(256) void conv_kernel(
    const float* __restrict__ x,
    const float* __restrict__ qw, const float* __restrict__ kw,
    const float* __restrict__ vw, const float* __restrict__ ow)
{
    const int z = blockIdx.y;
    const float* src;
    __half* dst;
    if (z < 4) {
        src = (z == 0) ? qw : ((z == 1) ? kw : ((z == 2) ? vw : ow));
        dst = g_w[z];
    } else {
        src = x   + (size_t)(z - 4) * (DD*DD);
        dst = g_xh + (size_t)(z - 4) * (DD*DD);
    }
    int i = (blockIdx.x * 256 + threadIdx.x) * 4;
    float4 v = *(const float4*)(src + i);
    ((__half2*)(dst + i))[0] = __floats2half2_rn(v.x, v.y);
    ((__half2*)(dst + i))[1] = __floats2half2_rn(v.z, v.w);
}

// ---------------------------------------------------------------------------
// HMMA GEMM, single fp16 pass: Y[m,n] = sum_k A[m,k]*B[n,k] + bias[n].
// CTA 128x128, 8 warps (64x32 warp tile), K-chunk 64, 2-stage cp.async,
// 1 sync/chunk. Epilogue: fp32 (Yf) or single fp16 (Yh).
// ---------------------------------------------------------------------------
#define GEMM_SMEM (2*32768)   // 2 stages x (A 16K + B 16K)

__device__ __forceinline__ void gemm_hmma(
    const __half* __restrict__ A, const __half* __restrict__ B,
    const float* __restrict__ bias, float* __restrict__ Yf,
    __half* __restrict__ Yh)
{
    extern __shared__ char sm[];
    const uint32_t sb = smem_u32(sm);
    const int tid = threadIdx.x;
    const int wid = tid >> 5, lane = tid & 31;
    const int warp_m = (wid >> 2) << 6;     // 0 / 64
    const int warp_n = (wid & 3) << 5;      // 0..96
    const int bm = blockIdx.y * 128, bn = blockIdx.x * 128;
    const int sub = lane >> 3, l7 = lane & 7;

    float acc[4][4][4];
#pragma unroll
    for (int mt = 0; mt < 4; mt++)
#pragma unroll
        for (int nt = 0; nt < 4; nt++)
#pragma unroll
            for (int j = 0; j < 4; j++) acc[mt][nt][j] = 0.f;

    auto load_chunk = [&](int c, int st) {
        const int kt = c * 64;
        const uint32_t stA = sb + st * 32768;
        const uint32_t stB = stA + 16384;
#pragma unroll
        for (int i = 0; i < 4; i++) {
            int gid = i * 256 + tid;
            int r = gid >> 3, g = gid & 7;
            cpa16(stA + SW(r, g), A + (size_t)(bm + r) * DD + kt + g * 8);
        }
#pragma unroll
        for (int i = 0; i < 4; i++) {
            int gid = i * 256 + tid;
            int r = gid >> 3, g = gid & 7;
            cpa16(stB + SW(r, g), B + (size_t)(bn + r) * DD + kt + g * 8);
        }
        CP_COMMIT();
    };

    load_chunk(0, 0);

    for (int c = 0; c < 16; c++) {
        const int st = c & 1;
        CP_WAIT(0);
        __syncthreads();
        if (c < 15) load_chunk(c + 1, st ^ 1);

        const uint32_t stA = sb + st * 32768;
        const uint32_t stB = stA + 16384;
#pragma unroll
        for (int ks = 0; ks < 4; ks++) {
            const int g = ks * 2 + (sub >> 1);
            uint32_t a[4][4];
#pragma unroll
            for (int mt = 0; mt < 4; mt++) {
                int row = warp_m + mt * 16 + ((sub & 1) << 3) + l7;
                ldm_x4(a[mt], stA + SW(row, g));
            }
#pragma unroll
            for (int hb = 0; hb < 2; hb++) {
                int row = warp_n + hb * 16 + ((sub & 1) << 3) + l7;
                uint32_t bq[4];
                ldm_x4(bq, stB + SW(row, g));
#pragma unroll
                for (int mt = 0; mt < 4; mt++) {
                    mma16816(acc[mt][hb*2],   a[mt], bq[0], bq[2]);
                    mma16816(acc[mt][hb*2+1], a[mt], bq[1], bq[3]);
                }
            }
        }
    }

    // Epilogue
    const int rq = lane >> 2, cq = (lane & 3) << 1;
#pragma unroll
    for (int mt = 0; mt < 4; mt++) {
        int row = bm + warp_m + mt * 16 + rq;
#pragma unroll
        for (int nt = 0; nt < 4; nt++) {
            int col = bn + warp_n + nt * 8 + cq;
            float b0 = __ldg(bias + col), b1 = __ldg(bias + col + 1);
            float y00 = acc[mt][nt][0] + b0, y01 = acc[mt][nt][1] + b1;
            float y10 = acc[mt][nt][2] + b0, y11 = acc[mt][nt][3] + b1;
            if (Yf) {
                *(float2*)(Yf + (size_t)row * DD + col)       = make_float2(y00, y01);
                *(float2*)(Yf + (size_t)(row + 8) * DD + col) = make_float2(y10, y11);
            } else {
                *(__half2*)(Yh + (size_t)row * DD + col)       = __floats2half2_rn(y00, y01);
                *(__half2*)(Yh + (size_t)(row + 8) * DD + col) = __floats2half2_rn(y10, y11);
            }
        }
    }
}

__global__ __launch_bounds__(256, 2) void qkv_hmma_kernel(
    const float* __restrict__ qb, const float* __restrict__ kb,
    const float* __restrict__ vb)
{
    const int z = blockIdx.z;
    if (z == 0)      gemm_hmma(g_xh, g_w[0], qb, g_q, 0);
    else if (z == 1) gemm_hmma(g_xh, g_w[1], kb, g_k, 0);
    else             gemm_hmma(g_xh, g_w[2], vb, 0, g_vh);
}
__global__ __launch_bounds__(256, 2) void oproj_hmma_kernel(
    const float* __restrict__ ob, float* __restrict__ out)
{
    gemm_hmma(g_oh, g_w[3], ob, out, 0);
}

// ---------------------------------------------------------------------------
// Per-head LayerNorm: Q (x0.125 folded) and K, both -> single fp16.
// ---------------------------------------------------------------------------
__global__ __launch_bounds__(256) void ln_kernel(
    const float* __restrict__ qg, const float* __restrict__ qb,
    const float* __restrict__ kg, const float* __restrict__ kb)
{
    const int warp = threadIdx.x >> 5;
    const int lane = threadIdx.x & 31;
    int row = blockIdx.x * 8 + warp;
    const int NR = BB*SS*HH;

    const bool isQ = (row < NR);
    const float* buf = isQ ? g_q : g_k;
    const float* g   = isQ ? qg : kg;
    const float* b   = isQ ? qb : kb;
    __half* dst      = isQ ? g_qh : g_kh;
    const float scale = isQ ? 0.125f : 1.f;
    if (!isQ) row -= NR;

    const float* p = buf + (size_t)row * HD;
    float x0 = p[lane], x1 = p[lane + 32];

    float s = x0 + x1;
#pragma unroll
    for (int off = 16; off; off >>= 1) s += __shfl_xor_sync(~0u, s, off);
    float mu = s * (1.f / 64.f);

    float d0 = x0 - mu, d1 = x1 - mu;
    float vv = d0*d0 + d1*d1;
#pragma unroll
    for (int off = 16; off; off >>= 1) vv += __shfl_xor_sync(~0u, vv, off);
    float rstd = rsqrtf(vv * (1.f / 64.f) + 1e-5f);

    float y0 = (d0 * rstd * g[lane]      + b[lane])      * scale;
    float y1 = (d1 * rstd * g[lane + 32] + b[lane + 32]) * scale;
    size_t off0 = (size_t)row * HD + lane;
    dst[off0]      = __float2half_rn(y0);
    dst[off0 + 32] = __float2half_rn(y1);
}

// ---------------------------------------------------------------------------
// Flash attention, HMMA fp16, all single-pass. 256 threads = 8 warps,
// q-tile 128 rows. K/V double-buffered, 1 sync/chunk. Output single fp16.
// Smem: Qh 16K + 2 stages x (K 8K + V 8K) = 48KB dynamic.
// ---------------------------------------------------------------------------
#define FLASH_SMEM (16384 + 2*16384)

__global__ __launch_bounds__(256, 2) void flash_hmma_kernel()
{
    extern __shared__ char fsm[];
    const uint32_t sb = smem_u32(fsm);
    const uint32_t QH = sb;

    const int tid = threadIdx.x;
    const int wid = tid >> 5, lane = tid & 31;
    const int sub = lane >> 3, l7 = lane & 7;
    const int rq = lane >> 2, cq = (lane & 3) << 1;
    const int b = blockIdx.z, h = blockIdx.y;
    const int q0 = blockIdx.x * 128;
    const size_t hbase = (size_t)b * SS * DD + (size_t)h * HD;

    // Load Q tile (128 rows) once
#pragma unroll
    for (int i = 0; i < 4; i++) {
        int gid = i * 256 + tid;
        int r = gid >> 3, g = gid & 7;
        cpa16(QH + SW(r, g), g_qh + hbase + (size_t)(q0 + r) * DD + g * 8);
    }
    CP_COMMIT();

    auto load_kv = [&](int c0, int st) {
        const uint32_t stage = sb + 16384 + st * 16384;
#pragma unroll
        for (int i = 0; i < 2; i++) {
            int gid = i * 256 + tid;
            int r = gid >> 3, g = gid & 7;
            cpa16(stage + SW(r, g),
                  g_kh + hbase + (size_t)(c0 + r) * DD + g * 8);
        }
#pragma unroll
        for (int i = 0; i < 2; i++) {
            int gid = i * 256 + tid;
            int r = gid >> 3, g = gid & 7;
            cpa16(stage + 8192 + SW(r, g),
                  g_vh + hbase + (size_t)(c0 + r) * DD + g * 8);
        }
        CP_COMMIT();
    };

    load_kv(0, 0);

    float o[8][4];
#pragma unroll
    for (int nt = 0; nt < 8; nt++)
#pragma unroll
        for (int j = 0; j < 4; j++) o[nt][j] = 0.f;
    float m0 = -1e30f, m1 = -1e30f, l0 = 0.f, l1 = 0.f;

    for (int cidx = 0; cidx < SS / 64; cidx++) {
        const int st = cidx & 1;
        CP_WAIT(0);
        __syncthreads();
        if (cidx + 1 < SS / 64) load_kv((cidx + 1) * 64, st ^ 1);

        const uint32_t stage = sb + 16384 + st * 16384;
        const uint32_t KS = stage, VS = stage + 8192;

        // ---- S = Q @ K^T : single-pass ----
        float s[8][4];
#pragma unroll
        for (int nt = 0; nt < 8; nt++)
#pragma unroll
            for (int j = 0; j < 4; j++) s[nt][j] = 0.f;

#pragma unroll
        for (int ks = 0; ks < 4; ks++) {
            const int g = ks * 2 + (sub >> 1);
            uint32_t ah[4];
            {
                int row = wid * 16 + ((sub & 1) << 3) + l7;
                ldm_x4(ah, QH + SW(row, g));
            }
#pragma unroll
            for (int nb = 0; nb < 4; nb++) {
                int row = nb * 16 + ((sub & 1) << 3) + l7;
                uint32_t kq[4];
                ldm_x4(kq, KS + SW(row, g));
                mma16816(s[nb*2],   ah, kq[0], kq[2]);
                mma16816(s[nb*2+1], ah, kq[1], kq[3]);
            }
        }

        // ---- online softmax ----
        float rmax0 = -1e30f, rmax1 = -1e30f;
#pragma unroll
        for (int nt = 0; nt < 8; nt++) {
            rmax0 = fmaxf(rmax0, fmaxf(s[nt][0], s[nt][1]));
            rmax1 = fmaxf(rmax1, fmaxf(s[nt][2], s[nt][3]));
        }
        rmax0 = fmaxf(rmax0, __shfl_xor_sync(~0u, rmax0, 1));
        rmax0 = fmaxf(rmax0, __shfl_xor_sync(~0u, rmax0, 2));
        rmax1 = fmaxf(rmax1, __shfl_xor_sync(~0u, rmax1, 1));
        rmax1 = fmaxf(rmax1, __shfl_xor_sync(~0u, rmax1, 2));

        float mn0 = fmaxf(m0, rmax0), mn1 = fmaxf(m1, rmax1);
        float corr0 = __expf(m0 - mn0), corr1 = __expf(m1 - mn1);
        m0 = mn0; m1 = mn1;

        float rs0 = 0.f, rs1 = 0.f;
#pragma unroll
        for (int nt = 0; nt < 8; nt++) {
            s[nt][0] = __expf(s[nt][0] - m0);
            s[nt][1] = __expf(s[nt][1] - m0);
            s[nt][2] = __expf(s[nt][2] - m1);
            s[nt][3] = __expf(s[nt][3] - m1);
            rs0 += s[nt][0] + s[nt][1];
            rs1 += s[nt][2] + s[nt][3];
        }
        rs0 += __shfl_xor_sync(~0u, rs0, 1); rs0 += __shfl_xor_sync(~0u, rs0, 2);
        rs1 += __shfl_xor_sync(~0u, rs1, 1); rs1 += __shfl_xor_sync(~0u, rs1, 2);
        l0 = l0 * corr0 + rs0;
        l1 = l1 * corr1 + rs1;
#pragma unroll
        for (int nt = 0; nt < 8; nt++) {
            o[nt][0] *= corr0; o[nt][1] *= corr0;
            o[nt][2] *= corr1; o[nt][3] *= corr1;
        }

        // ---- O += P @ V : single x single ----
#pragma unroll
        for (int kvt = 0; kvt < 4; kvt++) {
            const float* t0 = s[kvt*2];
            const float* t1 = s[kvt*2+1];
            uint32_t ph[4];
            ph[0] = pack_h2(t0[0], t0[1]);
            ph[1] = pack_h2(t0[2], t0[3]);
            ph[2] = pack_h2(t1[0], t1[1]);
            ph[3] = pack_h2(t1[2], t1[3]);
            int row = kvt * 16 + ((sub & 1) << 3) + l7;
#pragma unroll
            for (int db = 0; db < 4; db++) {
                int g = db * 2 + (sub >> 1);
                uint32_t vq[4];
                ldm_x4_t(vq, VS + SW(row, g));
                mma16816(o[db*2],   ph, vq[0], vq[1]);
                mma16816(o[db*2+1], ph, vq[2], vq[3]);
            }
        }
    }

    // ---- finalize: divide by l, write single fp16 ----
    float inv0 = 1.f / l0, inv1 = 1.f / l1;
    int row0 = q0 + wid * 16 + rq;
#pragma unroll
    for (int nt = 0; nt < 8; nt++) {
        int col = nt * 8 + cq;
        *(__half2*)(g_oh + hbase + (size_t)row0 * DD + col) =
            __floats2half2_rn(o[nt][0] * inv0, o[nt][1] * inv0);
        *(__half2*)(g_oh + hbase + (size_t)(row0 + 8) * DD + col) =
            __floats2half2_rn(o[nt][2] * inv1, o[nt][3] * inv1);
    }
}

// ---------------------------------------------------------------------------
extern "C" void kernel_launch(void* const* d_in, const int* in_sizes, int n_in,
                              void* d_out, int out_size)
{
    const float* x   = (const float*)d_in[0];
    const float* qw  = (const float*)d_in[1];
    const float* qb  = (const float*)d_in[2];
    const float* kw  = (const float*)d_in[3];
    const float* kb  = (const float*)d_in[4];
    const float* vw  = (const float*)d_in[5];
    const float* vb  = (const float*)d_in[6];
    const float* ow  = (const float*)d_in[7];
    const float* ob  = (const float*)d_in[8];
    const float* qlg = (const float*)d_in[9];
    const float* qlb = (const float*)d_in[10];
    const float* klg = (const float*)d_in[11];
    const float* klb = (const float*)d_in[12];
    float* out = (float*)d_out;

    cudaFuncSetAttribute(qkv_hmma_kernel,
                         cudaFuncAttributeMaxDynamicSharedMemorySize, GEMM_SMEM);
    cudaFuncSetAttribute(oproj_hmma_kernel,
                         cudaFuncAttributeMaxDynamicSharedMemorySize, GEMM_SMEM);
    cudaFuncSetAttribute(flash_hmma_kernel,
                         cudaFuncAttributeMaxDynamicSharedMemorySize, FLASH_SMEM);

    conv_kernel<<<dim3(DD*DD/1024, 8), 256>>>(x, qw, kw, vw, ow);

    qkv_hmma_kernel<<<dim3(DD/128, NTOK/128, 3), 256, GEMM_SMEM>>>(qb, kb, vb);
    ln_kernel<<<(2 * BB * SS * HH) / 8, 256>>>(qlg, qlb, klg, klb);
    flash_hmma_kernel<<<dim3(SS/128, HH, BB), 256, FLASH_SMEM>>>();
    oproj_hmma_kernel<<<dim3(DD/128, NTOK/128), 256, GEMM_SMEM>>>(ob, out);
}

// round 12
// speedup vs baseline: 2.7526x; 1.0585x over previous
#include <cuda_runtime.h>
#include <cuda_fp16.h>
#include <cstdint>

// Problem constants
#define BB 2
#define SS 2048
#define DD 1024
#define HH 16
#define HD 64
#define NTOK (BB*SS)   // 4096
#define LOG2E 1.4426950408889634f

// ---------------------------------------------------------------------------
// Scratch (__device__ globals per allocation rules).
// ---------------------------------------------------------------------------
__device__ __half g_xh[NTOK*DD];   // X (single fp16)
__device__ __half g_oh[NTOK*DD];   // attn-out (single fp16)
__device__ __half g_vh[NTOK*DD];   // V (single fp16)
__device__ __half g_qh[NTOK*DD];   // LN(Q)*0.125*log2e fp16
__device__ __half g_kh[NTOK*DD];   // LN(K) fp16
__device__ __half g_w[4][DD*DD];   // weights single fp16

// ---------------------------------------------------------------------------
// Helpers (sm_80-era instructions only)
// ---------------------------------------------------------------------------
__device__ __forceinline__ uint32_t smem_u32(const void* p) {
    uint32_t a;
    asm("{ .reg .u64 t; cvta.to.shared.u64 t, %1; cvt.u32.u64 %0, t; }"
        : "=r"(a) : "l"(p));
    return a;
}
__device__ __forceinline__ void cpa16(uint32_t dst, const void* src) {
    asm volatile("cp.async.cg.shared.global [%0], [%1], 16;" :: "r"(dst), "l"(src));
}
#define CP_COMMIT() asm volatile("cp.async.commit_group;" ::: "memory")
#define CP_WAIT(n)  asm volatile("cp.async.wait_group %0;" :: "n"(n) : "memory")

__device__ __forceinline__ void ldm_x4(uint32_t* r, uint32_t addr) {
    asm volatile("ldmatrix.sync.aligned.m8n8.x4.shared.b16 {%0,%1,%2,%3}, [%4];"
                 : "=r"(r[0]), "=r"(r[1]), "=r"(r[2]), "=r"(r[3]) : "r"(addr));
}
__device__ __forceinline__ void ldm_x4_t(uint32_t* r, uint32_t addr) {
    asm volatile("ldmatrix.sync.aligned.m8n8.x4.trans.shared.b16 {%0,%1,%2,%3}, [%4];"
                 : "=r"(r[0]), "=r"(r[1]), "=r"(r[2]), "=r"(r[3]) : "r"(addr));
}
__device__ __forceinline__ void mma16816(float* d, const uint32_t* a,
                                         uint32_t b0, uint32_t b1) {
    asm volatile(
        "mma.sync.aligned.m16n8k16.row.col.f32.f16.f16.f32 "
        "{%0,%1,%2,%3}, {%4,%5,%6,%7}, {%8,%9}, {%0,%1,%2,%3};"
        : "+f"(d[0]), "+f"(d[1]), "+f"(d[2]), "+f"(d[3])
        : "r"(a[0]), "r"(a[1]), "r"(a[2]), "r"(a[3]), "r"(b0), "r"(b1));
}
__device__ __forceinline__ uint32_t pack_h2(float lo, float hi) {
    __half2 t = __floats2half2_rn(lo, hi);
    return *(uint32_t*)&t;
}
__device__ __forceinline__ float ex2(float x) {
    float r;
    asm("ex2.approx.ftz.f32 %0, %1;" : "=f"(r) : "f"(x));
    return r;
}
// swizzled byte offset within a tile of 128B rows, 16B granules g=0..7
#define SW(r, g) ((r)*128 + ((((g) ^ ((r)&7))) << 4))

// ---------------------------------------------------------------------------
// Unified fp32 -> fp16 conversion: slab z = 0..3 weights, 4..7 X quarters.
// ---------------------------------------------------------------------------
__global__ __launch_bounds__(256) void conv_kernel(
    const float* __restrict__ x,
    const float* __restrict__ qw, const float* __restrict__ kw,
    const float* __restrict__ vw, const float* __restrict__ ow)
{
    const int z = blockIdx.y;
    const float* src;
    __half* dst;
    if (z < 4) {
        src = (z == 0) ? qw : ((z == 1) ? kw : ((z == 2) ? vw : ow));
        dst = g_w[z];
    } else {
        src = x    + (size_t)(z - 4) * (DD*DD);
        dst = g_xh + (size_t)(z - 4) * (DD*DD);
    }
    int i = (blockIdx.x * 256 + threadIdx.x) * 4;
    float4 v = *(const float4*)(src + i);
    ((__half2*)(dst + i))[0] = __floats2half2_rn(v.x, v.y);
    ((__half2*)(dst + i))[1] = __floats2half2_rn(v.z, v.w);
}

// ---------------------------------------------------------------------------
// HMMA GEMM, single fp16 pass: Y[m,n] = sum_k A[m,k]*B[n,k] + bias[n].
// CTA 128x128, 8 warps (64x32 warp tile), K-chunk 64, 2-stage cp.async,
// 1 sync/chunk.
// MODE 0: fp32 out (Yf). MODE 1: fp16 out (Yh).
// MODE 2: fused per-head LayerNorm (gamma/beta over HD=64) * scale -> fp16.
//         Tile staged in smem fp32 (stride 132), one thread per (row, head).
// ---------------------------------------------------------------------------
#define GEMM_SMEM 67584   // max(2*32768 stages, 128*132*4 LN staging)

template <int MODE>
__device__ __forceinline__ void gemm_hmma(
    const __half* __restrict__ A, const __half* __restrict__ B,
    const float* __restrict__ bias, float* __restrict__ Yf,
    __half* __restrict__ Yh,
    const float* __restrict__ lng, const float* __restrict__ lnb,
    float lnscale)
{
    extern __shared__ char sm[];
    const uint32_t sb = smem_u32(sm);
    const int tid = threadIdx.x;
    const int wid = tid >> 5, lane = tid & 31;
    const int warp_m = (wid >> 2) << 6;     // 0 / 64
    const int warp_n = (wid & 3) << 5;      // 0..96
    const int bm = blockIdx.y * 128, bn = blockIdx.x * 128;
    const int sub = lane >> 3, l7 = lane & 7;

    float acc[4][4][4];
#pragma unroll
    for (int mt = 0; mt < 4; mt++)
#pragma unroll
        for (int nt = 0; nt < 4; nt++)
#pragma unroll
            for (int j = 0; j < 4; j++) acc[mt][nt][j] = 0.f;

    auto load_chunk = [&](int c, int st) {
        const int kt = c * 64;
        const uint32_t stA = sb + st * 32768;
        const uint32_t stB = stA + 16384;
#pragma unroll
        for (int i = 0; i < 4; i++) {
            int gid = i * 256 + tid;
            int r = gid >> 3, g = gid & 7;
            cpa16(stA + SW(r, g), A + (size_t)(bm + r) * DD + kt + g * 8);
        }
#pragma unroll
        for (int i = 0; i < 4; i++) {
            int gid = i * 256 + tid;
            int r = gid >> 3, g = gid & 7;
            cpa16(stB + SW(r, g), B + (size_t)(bn + r) * DD + kt + g * 8);
        }
        CP_COMMIT();
    };

    load_chunk(0, 0);

    for (int c = 0; c < 16; c++) {
        const int st = c & 1;
        CP_WAIT(0);
        __syncthreads();
        if (c < 15) load_chunk(c + 1, st ^ 1);

        const uint32_t stA = sb + st * 32768;
        const uint32_t stB = stA + 16384;
#pragma unroll
        for (int ks = 0; ks < 4; ks++) {
            const int g = ks * 2 + (sub >> 1);
            uint32_t a[4][4];
#pragma unroll
            for (int mt = 0; mt < 4; mt++) {
                int row = warp_m + mt * 16 + ((sub & 1) << 3) + l7;
                ldm_x4(a[mt], stA + SW(row, g));
            }
#pragma unroll
            for (int hb = 0; hb < 2; hb++) {
                int row = warp_n + hb * 16 + ((sub & 1) << 3) + l7;
                uint32_t bq[4];
                ldm_x4(bq, stB + SW(row, g));
#pragma unroll
                for (int mt = 0; mt < 4; mt++) {
                    mma16816(acc[mt][hb*2],   a[mt], bq[0], bq[2]);
                    mma16816(acc[mt][hb*2+1], a[mt], bq[1], bq[3]);
                }
            }
        }
    }

    const int rq = lane >> 2, cq = (lane & 3) << 1;

    if (MODE == 2) {
        // ---- stage tile (+bias) into smem fp32, stride 132 ----
        float* eps = (float*)sm;
        __syncthreads();   // all warps done with ldmatrix on stage smem
#pragma unroll
        for (int mt = 0; mt < 4; mt++) {
            int row = warp_m + mt * 16 + rq;
#pragma unroll
            for (int nt = 0; nt < 4; nt++) {
                int col = warp_n + nt * 8 + cq;
                float b0 = __ldg(bias + bn + col), b1 = __ldg(bias + bn + col + 1);
                eps[row * 132 + col]           = acc[mt][nt][0] + b0;
                eps[row * 132 + col + 1]       = acc[mt][nt][1] + b1;
                eps[(row + 8) * 132 + col]     = acc[mt][nt][2] + b0;
                eps[(row + 8) * 132 + col + 1] = acc[mt][nt][3] + b1;
            }
        }
        __syncthreads();

        // ---- one thread per (row, head): LN over 64 cols, write fp16 ----
        const int row  = tid >> 1;
        const int head = tid & 1;
        const float* t = eps + row * 132 + head * 64;
        float sum = 0.f, sq = 0.f;
#pragma unroll
        for (int j = 0; j < 64; j++) {
            float v = t[j];
            sum += v; sq += v * v;
        }
        float mu = sum * (1.f / 64.f);
        float var = sq * (1.f / 64.f) - mu * mu;
        float rstd = rsqrtf(var + 1e-5f);
        __half* dst = Yh + (size_t)(bm + row) * DD + bn + head * 64;
#pragma unroll
        for (int j = 0; j < 64; j += 2) {
            float y0 = ((t[j]   - mu) * rstd * __ldg(lng + j)   + __ldg(lnb + j))   * lnscale;
            float y1 = ((t[j+1] - mu) * rstd * __ldg(lng + j+1) + __ldg(lnb + j+1)) * lnscale;
            *(__half2*)(dst + j) = __floats2half2_rn(y0, y1);
        }
    } else {
#pragma unroll
        for (int mt = 0; mt < 4; mt++) {
            int row = bm + warp_m + mt * 16 + rq;
#pragma unroll
            for (int nt = 0; nt < 4; nt++) {
                int col = bn + warp_n + nt * 8 + cq;
                float b0 = __ldg(bias + col), b1 = __ldg(bias + col + 1);
                float y00 = acc[mt][nt][0] + b0, y01 = acc[mt][nt][1] + b1;
                float y10 = acc[mt][nt][2] + b0, y11 = acc[mt][nt][3] + b1;
                if (MODE == 0) {
                    *(float2*)(Yf + (size_t)row * DD + col)       = make_float2(y00, y01);
                    *(float2*)(Yf + (size_t)(row + 8) * DD + col) = make_float2(y10, y11);
                } else {
                    *(__half2*)(Yh + (size_t)row * DD + col)       = __floats2half2_rn(y00, y01);
                    *(__half2*)(Yh + (size_t)(row + 8) * DD + col) = __floats2half2_rn(y10, y11);
                }
            }
        }
    }
}

__global__ __launch_bounds__(256, 2) void qkv_hmma_kernel(
    const float* __restrict__ qb, const float* __restrict__ kb,
    const float* __restrict__ vb,
    const float* __restrict__ qlg, const float* __restrict__ qlb,
    const float* __restrict__ klg, const float* __restrict__ klb)
{
    const int z = blockIdx.z;
    if (z == 0)
        gemm_hmma<2>(g_xh, g_w[0], qb, 0, g_qh, qlg, qlb, 0.125f * LOG2E);
    else if (z == 1)
        gemm_hmma<2>(g_xh, g_w[1], kb, 0, g_kh, klg, klb, 1.f);
    else
        gemm_hmma<1>(g_xh, g_w[2], vb, 0, g_vh, 0, 0, 0.f);
}
__global__ __launch_bounds__(256, 2) void oproj_hmma_kernel(
    const float* __restrict__ ob, float* __restrict__ out)
{
    gemm_hmma<0>(g_oh, g_w[3], ob, out, 0, 0, 0, 0.f);
}

// ---------------------------------------------------------------------------
// Flash attention, HMMA fp16, all single-pass, exp2 domain (Q prescaled by
// 0.125*log2e in the LN epilogue). 256 threads = 8 warps, q-tile 128 rows.
// K/V double-buffered, 1 sync/chunk. Output single fp16.
// Smem: Qh 16K + 2 stages x (K 8K + V 8K) = 48KB dynamic.
// ---------------------------------------------------------------------------
#define FLASH_SMEM (16384 + 2*16384)

__global__ __launch_bounds__(256, 2) void flash_hmma_kernel()
{
    extern __shared__ char fsm[];
    const uint32_t sb = smem_u32(fsm);
    const uint32_t QH = sb;

    const int tid = threadIdx.x;
    const int wid = tid >> 5, lane = tid & 31;
    const int sub = lane >> 3, l7 = lane & 7;
    const int rq = lane >> 2, cq = (lane & 3) << 1;
    const int b = blockIdx.z, h = blockIdx.y;
    const int q0 = blockIdx.x * 128;
    const size_t hbase = (size_t)b * SS * DD + (size_t)h * HD;

    // Load Q tile (128 rows) once
#pragma unroll
    for (int i = 0; i < 4; i++) {
        int gid = i * 256 + tid;
        int r = gid >> 3, g = gid & 7;
        cpa16(QH + SW(r, g), g_qh + hbase + (size_t)(q0 + r) * DD + g * 8);
    }
    CP_COMMIT();

    auto load_kv = [&](int c0, int st) {
        const uint32_t stage = sb + 16384 + st * 16384;
#pragma unroll
        for (int i = 0; i < 2; i++) {
            int gid = i * 256 + tid;
            int r = gid >> 3, g = gid & 7;
            cpa16(stage + SW(r, g),
                  g_kh + hbase + (size_t)(c0 + r) * DD + g * 8);
        }
#pragma unroll
        for (int i = 0; i < 2; i++) {
            int gid = i * 256 + tid;
            int r = gid >> 3, g = gid & 7;
            cpa16(stage + 8192 + SW(r, g),
                  g_vh + hbase + (size_t)(c0 + r) * DD + g * 8);
        }
        CP_COMMIT();
    };

    load_kv(0, 0);

    float o[8][4];
#pragma unroll
    for (int nt = 0; nt < 8; nt++)
#pragma unroll
        for (int j = 0; j < 4; j++) o[nt][j] = 0.f;
    float m0 = -1e30f, m1 = -1e30f, l0 = 0.f, l1 = 0.f;

    for (int cidx = 0; cidx < SS / 64; cidx++) {
        const int st = cidx & 1;
        CP_WAIT(0);
        __syncthreads();
        if (cidx + 1 < SS / 64) load_kv((cidx + 1) * 64, st ^ 1);

        const uint32_t stage = sb + 16384 + st * 16384;
        const uint32_t KS = stage, VS = stage + 8192;

        // ---- S = Q @ K^T (log2 domain) ----
        float s[8][4];
#pragma unroll
        for (int nt = 0; nt < 8; nt++)
#pragma unroll
            for (int j = 0; j < 4; j++) s[nt][j] = 0.f;

#pragma unroll
        for (int ks = 0; ks < 4; ks++) {
            const int g = ks * 2 + (sub >> 1);
            uint32_t ah[4];
            {
                int row = wid * 16 + ((sub & 1) << 3) + l7;
                ldm_x4(ah, QH + SW(row, g));
            }
#pragma unroll
            for (int nb = 0; nb < 4; nb++) {
                int row = nb * 16 + ((sub & 1) << 3) + l7;
                uint32_t kq[4];
                ldm_x4(kq, KS + SW(row, g));
                mma16816(s[nb*2],   ah, kq[0], kq[2]);
                mma16816(s[nb*2+1], ah, kq[1], kq[3]);
            }
        }

        // ---- online softmax, exp2 domain ----
        float rmax0 = -1e30f, rmax1 = -1e30f;
#pragma unroll
        for (int nt = 0; nt < 8; nt++) {
            rmax0 = fmaxf(rmax0, fmaxf(s[nt][0], s[nt][1]));
            rmax1 = fmaxf(rmax1, fmaxf(s[nt][2], s[nt][3]));
        }
        rmax0 = fmaxf(rmax0, __shfl_xor_sync(~0u, rmax0, 1));
        rmax0 = fmaxf(rmax0, __shfl_xor_sync(~0u, rmax0, 2));
        rmax1 = fmaxf(rmax1, __shfl_xor_sync(~0u, rmax1, 1));
        rmax1 = fmaxf(rmax1, __shfl_xor_sync(~0u, rmax1, 2));

        float mn0 = fmaxf(m0, rmax0), mn1 = fmaxf(m1, rmax1);
        float corr0 = ex2(m0 - mn0), corr1 = ex2(m1 - mn1);
        m0 = mn0; m1 = mn1;

        float rs0 = 0.f, rs1 = 0.f;
#pragma unroll
        for (int nt = 0; nt < 8; nt++) {
            s[nt][0] = ex2(s[nt][0] - m0);
            s[nt][1] = ex2(s[nt][1] - m0);
            s[nt][2] = ex2(s[nt][2] - m1);
            s[nt][3] = ex2(s[nt][3] - m1);
            rs0 += s[nt][0] + s[nt][1];
            rs1 += s[nt][2] + s[nt][3];
        }
        rs0 += __shfl_xor_sync(~0u, rs0, 1); rs0 += __shfl_xor_sync(~0u, rs0, 2);
        rs1 += __shfl_xor_sync(~0u, rs1, 1); rs1 += __shfl_xor_sync(~0u, rs1, 2);
        l0 = l0 * corr0 + rs0;
        l1 = l1 * corr1 + rs1;
#pragma unroll
        for (int nt = 0; nt < 8; nt++) {
            o[nt][0] *= corr0; o[nt][1] *= corr0;
            o[nt][2] *= corr1; o[nt][3] *= corr1;
        }

        // ---- O += P @ V ----
#pragma unroll
        for (int kvt = 0; kvt < 4; kvt++) {
            const float* t0 = s[kvt*2];
            const float* t1 = s[kvt*2+1];
            uint32_t ph[4];
            ph[0] = pack_h2(t0[0], t0[1]);
            ph[1] = pack_h2(t0[2], t0[3]);
            ph[2] = pack_h2(t1[0], t1[1]);
            ph[3] = pack_h2(t1[2], t1[3]);
            int row = kvt * 16 + ((sub & 1) << 3) + l7;
#pragma unroll
            for (int db = 0; db < 4; db++) {
                int g = db * 2 + (sub >> 1);
                uint32_t vq[4];
                ldm_x4_t(vq, VS + SW(row, g));
                mma16816(o[db*2],   ph, vq[0], vq[1]);
                mma16816(o[db*2+1], ph, vq[2], vq[3]);
            }
        }
    }

    // ---- finalize: divide by l, write single fp16 ----
    float inv0 = 1.f / l0, inv1 = 1.f / l1;
    int row0 = q0 + wid * 16 + rq;
#pragma unroll
    for (int nt = 0; nt < 8; nt++) {
        int col = nt * 8 + cq;
        *(__half2*)(g_oh + hbase + (size_t)row0 * DD + col) =
            __floats2half2_rn(o[nt][0] * inv0, o[nt][1] * inv0);
        *(__half2*)(g_oh + hbase + (size_t)(row0 + 8) * DD + col) =
            __floats2half2_rn(o[nt][2] * inv1, o[nt][3] * inv1);
    }
}

// ---------------------------------------------------------------------------
extern "C" void kernel_launch(void* const* d_in, const int* in_sizes, int n_in,
                              void* d_out, int out_size)
{
    const float* x   = (const float*)d_in[0];
    const float* qw  = (const float*)d_in[1];
    const float* qb  = (const float*)d_in[2];
    const float* kw  = (const float*)d_in[3];
    const float* kb  = (const float*)d_in[4];
    const float* vw  = (const float*)d_in[5];
    const float* vb  = (const float*)d_in[6];
    const float* ow  = (const float*)d_in[7];
    const float* ob  = (const float*)d_in[8];
    const float* qlg = (const float*)d_in[9];
    const float* qlb = (const float*)d_in[10];
    const float* klg = (const float*)d_in[11];
    const float* klb = (const float*)d_in[12];
    float* out = (float*)d_out;

    cudaFuncSetAttribute(qkv_hmma_kernel,
                         cudaFuncAttributeMaxDynamicSharedMemorySize, GEMM_SMEM);
    cudaFuncSetAttribute(oproj_hmma_kernel,
                         cudaFuncAttributeMaxDynamicSharedMemorySize, GEMM_SMEM);
    cudaFuncSetAttribute(flash_hmma_kernel,
                         cudaFuncAttributeMaxDynamicSharedMemorySize, FLASH_SMEM);

    conv_kernel<<<dim3(DD*DD/1024, 8), 256>>>(x, qw, kw, vw, ow);

    qkv_hmma_kernel<<<dim3(DD/128, NTOK/128, 3), 256, GEMM_SMEM>>>(
        qb, kb, vb, qlg, qlb, klg, klb);
    flash_hmma_kernel<<<dim3(SS/128, HH, BB), 256, FLASH_SMEM>>>();
    oproj_hmma_kernel<<<dim3(DD/128, NTOK/128), 256, GEMM_SMEM>>>(ob, out);
}

// round 13
// speedup vs baseline: 2.8810x; 1.0466x over previous
#include <cuda_runtime.h>
#include <cuda_fp16.h>
#include <cstdint>

// Problem constants
#define BB 2
#define SS 2048
#define DD 1024
#define HH 16
#define HD 64
#define NTOK (BB*SS)   // 4096
#define LOG2E 1.4426950408889634f

// ---------------------------------------------------------------------------
// Scratch (__device__ globals per allocation rules).
// ---------------------------------------------------------------------------
__device__ __half g_xh[NTOK*DD];   // X (single fp16)
__device__ __half g_oh[NTOK*DD];   // attn-out (single fp16)
__device__ __half g_vh[NTOK*DD];   // V (single fp16)
__device__ __half g_qh[NTOK*DD];   // LN(Q)*0.125*log2e fp16
__device__ __half g_kh[NTOK*DD];   // LN(K) fp16
__device__ __half g_w[4][DD*DD];   // weights single fp16

// ---------------------------------------------------------------------------
// Helpers (sm_80-era instructions only)
// ---------------------------------------------------------------------------
__device__ __forceinline__ uint32_t smem_u32(const void* p) {
    uint32_t a;
    asm("{ .reg .u64 t; cvta.to.shared.u64 t, %1; cvt.u32.u64 %0, t; }"
        : "=r"(a) : "l"(p));
    return a;
}
__device__ __forceinline__ void cpa16(uint32_t dst, const void* src) {
    asm volatile("cp.async.cg.shared.global [%0], [%1], 16;" :: "r"(dst), "l"(src));
}
#define CP_COMMIT() asm volatile("cp.async.commit_group;" ::: "memory")
#define CP_WAIT(n)  asm volatile("cp.async.wait_group %0;" :: "n"(n) : "memory")

__device__ __forceinline__ void ldm_x4(uint32_t* r, uint32_t addr) {
    asm volatile("ldmatrix.sync.aligned.m8n8.x4.shared.b16 {%0,%1,%2,%3}, [%4];"
                 : "=r"(r[0]), "=r"(r[1]), "=r"(r[2]), "=r"(r[3]) : "r"(addr));
}
__device__ __forceinline__ void ldm_x4_t(uint32_t* r, uint32_t addr) {
    asm volatile("ldmatrix.sync.aligned.m8n8.x4.trans.shared.b16 {%0,%1,%2,%3}, [%4];"
                 : "=r"(r[0]), "=r"(r[1]), "=r"(r[2]), "=r"(r[3]) : "r"(addr));
}
__device__ __forceinline__ void mma16816(float* d, const uint32_t* a,
                                         uint32_t b0, uint32_t b1) {
    asm volatile(
        "mma.sync.aligned.m16n8k16.row.col.f32.f16.f16.f32 "
        "{%0,%1,%2,%3}, {%4,%5,%6,%7}, {%8,%9}, {%0,%1,%2,%3};"
        : "+f"(d[0]), "+f"(d[1]), "+f"(d[2]), "+f"(d[3])
        : "r"(a[0]), "r"(a[1]), "r"(a[2]), "r"(a[3]), "r"(b0), "r"(b1));
}
__device__ __forceinline__ uint32_t pack_h2(float lo, float hi) {
    __half2 t = __floats2half2_rn(lo, hi);
    return *(uint32_t*)&t;
}
__device__ __forceinline__ float ex2(float x) {
    float r;
    asm("ex2.approx.ftz.f32 %0, %1;" : "=f"(r) : "f"(x));
    return r;
}
// swizzled byte offset within a tile of 128B rows, 16B granules g=0..7
#define SW(r, g) ((r)*128 + ((((g) ^ ((r)&7))) << 4))

// ---------------------------------------------------------------------------
// Unified fp32 -> fp16 conversion: slab z = 0..3 weights, 4..7 X quarters.
// ---------------------------------------------------------------------------
__global__ __launch_bounds__(256) void conv_kernel(
    const float* __restrict__ x,
    const float* __restrict__ qw, const float* __restrict__ kw,
    const float* __restrict__ vw, const float* __restrict__ ow)
{
    const int z = blockIdx.y;
    const float* src;
    __half* dst;
    if (z < 4) {
        src = (z == 0) ? qw : ((z == 1) ? kw : ((z == 2) ? vw : ow));
        dst = g_w[z];
    } else {
        src = x    + (size_t)(z - 4) * (DD*DD);
        dst = g_xh + (size_t)(z - 4) * (DD*DD);
    }
    int i = (blockIdx.x * 256 + threadIdx.x) * 4;
    float4 v = *(const float4*)(src + i);
    ((__half2*)(dst + i))[0] = __floats2half2_rn(v.x, v.y);
    ((__half2*)(dst + i))[1] = __floats2half2_rn(v.z, v.w);
}

// ---------------------------------------------------------------------------
// HMMA GEMM, single fp16 pass, 3-stage cp.async pipeline (WAIT(1)):
// Y[m,n] = sum_k A[m,k]*B[n,k] + bias[n]. CTA 128x128, 8 warps, K-chunk 64.
// MODE 0: fp32 out. MODE 1: fp16 out. MODE 2: fused per-head LN -> fp16.
// ---------------------------------------------------------------------------
#define GEMM_SMEM (3*32768)   // 3 stages x (A 16K + B 16K); LN staging 67584 fits

template <int MODE>
__device__ __forceinline__ void gemm_hmma(
    const __half* __restrict__ A, const __half* __restrict__ B,
    const float* __restrict__ bias, float* __restrict__ Yf,
    __half* __restrict__ Yh,
    const float* __restrict__ lng, const float* __restrict__ lnb,
    float lnscale)
{
    extern __shared__ char sm[];
    const uint32_t sb = smem_u32(sm);
    const int tid = threadIdx.x;
    const int wid = tid >> 5, lane = tid & 31;
    const int warp_m = (wid >> 2) << 6;     // 0 / 64
    const int warp_n = (wid & 3) << 5;      // 0..96
    const int bm = blockIdx.y * 128, bn = blockIdx.x * 128;
    const int sub = lane >> 3, l7 = lane & 7;

    float acc[4][4][4];
#pragma unroll
    for (int mt = 0; mt < 4; mt++)
#pragma unroll
        for (int nt = 0; nt < 4; nt++)
#pragma unroll
            for (int j = 0; j < 4; j++) acc[mt][nt][j] = 0.f;

    auto load_chunk = [&](int c, int st) {
        const int kt = c * 64;
        const uint32_t stA = sb + st * 32768;
        const uint32_t stB = stA + 16384;
#pragma unroll
        for (int i = 0; i < 4; i++) {
            int gid = i * 256 + tid;
            int r = gid >> 3, g = gid & 7;
            cpa16(stA + SW(r, g), A + (size_t)(bm + r) * DD + kt + g * 8);
        }
#pragma unroll
        for (int i = 0; i < 4; i++) {
            int gid = i * 256 + tid;
            int r = gid >> 3, g = gid & 7;
            cpa16(stB + SW(r, g), B + (size_t)(bn + r) * DD + kt + g * 8);
        }
        CP_COMMIT();
    };

    load_chunk(0, 0);
    load_chunk(1, 1);

    for (int c = 0; c < 16; c++) {
        const int st = c % 3;
        CP_WAIT(1);          // stage c complete; c+1 may still be in flight
        __syncthreads();
        if (c < 14) load_chunk(c + 2, (c + 2) % 3);

        const uint32_t stA = sb + st * 32768;
        const uint32_t stB = stA + 16384;
#pragma unroll
        for (int ks = 0; ks < 4; ks++) {
            const int g = ks * 2 + (sub >> 1);
            uint32_t a[4][4];
#pragma unroll
            for (int mt = 0; mt < 4; mt++) {
                int row = warp_m + mt * 16 + ((sub & 1) << 3) + l7;
                ldm_x4(a[mt], stA + SW(row, g));
            }
#pragma unroll
            for (int hb = 0; hb < 2; hb++) {
                int row = warp_n + hb * 16 + ((sub & 1) << 3) + l7;
                uint32_t bq[4];
                ldm_x4(bq, stB + SW(row, g));
#pragma unroll
                for (int mt = 0; mt < 4; mt++) {
                    mma16816(acc[mt][hb*2],   a[mt], bq[0], bq[2]);
                    mma16816(acc[mt][hb*2+1], a[mt], bq[1], bq[3]);
                }
            }
        }
    }
    CP_WAIT(0);   // drain (last chunk's extra in-flight group, if any)

    const int rq = lane >> 2, cq = (lane & 3) << 1;

    if (MODE == 2) {
        // ---- stage tile (+bias) into smem fp32, stride 132 ----
        float* eps = (float*)sm;
        __syncthreads();   // all warps done with ldmatrix on stage smem
#pragma unroll
        for (int mt = 0; mt < 4; mt++) {
            int row = warp_m + mt * 16 + rq;
#pragma unroll
            for (int nt = 0; nt < 4; nt++) {
                int col = warp_n + nt * 8 + cq;
                float b0 = __ldg(bias + bn + col), b1 = __ldg(bias + bn + col + 1);
                eps[row * 132 + col]           = acc[mt][nt][0] + b0;
                eps[row * 132 + col + 1]       = acc[mt][nt][1] + b1;
                eps[(row + 8) * 132 + col]     = acc[mt][nt][2] + b0;
                eps[(row + 8) * 132 + col + 1] = acc[mt][nt][3] + b1;
            }
        }
        __syncthreads();

        // ---- one thread per (row, head): LN over 64 cols, write fp16 ----
        const int row  = tid >> 1;
        const int head = tid & 1;
        const float* t = eps + row * 132 + head * 64;
        float sum = 0.f, sq = 0.f;
#pragma unroll
        for (int j = 0; j < 64; j++) {
            float v = t[j];
            sum += v; sq += v * v;
        }
        float mu = sum * (1.f / 64.f);
        float var = sq * (1.f / 64.f) - mu * mu;
        float rstd = rsqrtf(var + 1e-5f);
        __half* dst = Yh + (size_t)(bm + row) * DD + bn + head * 64;
#pragma unroll
        for (int j = 0; j < 64; j += 2) {
            float y0 = ((t[j]   - mu) * rstd * __ldg(lng + j)   + __ldg(lnb + j))   * lnscale;
            float y1 = ((t[j+1] - mu) * rstd * __ldg(lng + j+1) + __ldg(lnb + j+1)) * lnscale;
            *(__half2*)(dst + j) = __floats2half2_rn(y0, y1);
        }
    } else {
#pragma unroll
        for (int mt = 0; mt < 4; mt++) {
            int row = bm + warp_m + mt * 16 + rq;
#pragma unroll
            for (int nt = 0; nt < 4; nt++) {
                int col = bn + warp_n + nt * 8 + cq;
                float b0 = __ldg(bias + col), b1 = __ldg(bias + col + 1);
                float y00 = acc[mt][nt][0] + b0, y01 = acc[mt][nt][1] + b1;
                float y10 = acc[mt][nt][2] + b0, y11 = acc[mt][nt][3] + b1;
                if (MODE == 0) {
                    *(float2*)(Yf + (size_t)row * DD + col)       = make_float2(y00, y01);
                    *(float2*)(Yf + (size_t)(row + 8) * DD + col) = make_float2(y10, y11);
                } else {
                    *(__half2*)(Yh + (size_t)row * DD + col)       = __floats2half2_rn(y00, y01);
                    *(__half2*)(Yh + (size_t)(row + 8) * DD + col) = __floats2half2_rn(y10, y11);
                }
            }
        }
    }
}

__global__ __launch_bounds__(256, 2) void qkv_hmma_kernel(
    const float* __restrict__ qb, const float* __restrict__ kb,
    const float* __restrict__ vb,
    const float* __restrict__ qlg, const float* __restrict__ qlb,
    const float* __restrict__ klg, const float* __restrict__ klb)
{
    const int z = blockIdx.z;
    if (z == 0)
        gemm_hmma<2>(g_xh, g_w[0], qb, 0, g_qh, qlg, qlb, 0.125f * LOG2E);
    else if (z == 1)
        gemm_hmma<2>(g_xh, g_w[1], kb, 0, g_kh, klg, klb, 1.f);
    else
        gemm_hmma<1>(g_xh, g_w[2], vb, 0, g_vh, 0, 0, 0.f);
}
__global__ __launch_bounds__(256, 2) void oproj_hmma_kernel(
    const float* __restrict__ ob, float* __restrict__ out)
{
    gemm_hmma<0>(g_oh, g_w[3], ob, out, 0, 0, 0, 0.f);
}

// ---------------------------------------------------------------------------
// Flash attention, HMMA fp16, exp2 domain. 128 threads = 4 warps,
// q-tile 64 rows (4 CTAs/SM for cross-CTA latency hiding).
// K/V double-buffered, 1 sync/chunk. Output single fp16.
// Smem: Qh 8K + 2 stages x (K 8K + V 8K) = 40KB dynamic.
// ---------------------------------------------------------------------------
#define FLASH_SMEM (8192 + 2*16384)

__global__ __launch_bounds__(128, 4) void flash_hmma_kernel()
{
    extern __shared__ char fsm[];
    const uint32_t sb = smem_u32(fsm);
    const uint32_t QH = sb;

    const int tid = threadIdx.x;
    const int wid = tid >> 5, lane = tid & 31;
    const int sub = lane >> 3, l7 = lane & 7;
    const int rq = lane >> 2, cq = (lane & 3) << 1;
    const int b = blockIdx.z, h = blockIdx.y;
    const int q0 = blockIdx.x * 64;
    const size_t hbase = (size_t)b * SS * DD + (size_t)h * HD;

    // Load Q tile (64 rows) once: 512 granules over 128 threads
#pragma unroll
    for (int i = 0; i < 4; i++) {
        int gid = i * 128 + tid;
        int r = gid >> 3, g = gid & 7;
        cpa16(QH + SW(r, g), g_qh + hbase + (size_t)(q0 + r) * DD + g * 8);
    }
    CP_COMMIT();

    auto load_kv = [&](int c0, int st) {
        const uint32_t stage = sb + 8192 + st * 16384;
#pragma unroll
        for (int i = 0; i < 4; i++) {
            int gid = i * 128 + tid;
            int r = gid >> 3, g = gid & 7;
            cpa16(stage + SW(r, g),
                  g_kh + hbase + (size_t)(c0 + r) * DD + g * 8);
        }
#pragma unroll
        for (int i = 0; i < 4; i++) {
            int gid = i * 128 + tid;
            int r = gid >> 3, g = gid & 7;
            cpa16(stage + 8192 + SW(r, g),
                  g_vh + hbase + (size_t)(c0 + r) * DD + g * 8);
        }
        CP_COMMIT();
    };

    load_kv(0, 0);

    float o[8][4];
#pragma unroll
    for (int nt = 0; nt < 8; nt++)
#pragma unroll
        for (int j = 0; j < 4; j++) o[nt][j] = 0.f;
    float m0 = -1e30f, m1 = -1e30f, l0 = 0.f, l1 = 0.f;

    for (int cidx = 0; cidx < SS / 64; cidx++) {
        const int st = cidx & 1;
        CP_WAIT(0);
        __syncthreads();
        if (cidx + 1 < SS / 64) load_kv((cidx + 1) * 64, st ^ 1);

        const uint32_t stage = sb + 8192 + st * 16384;
        const uint32_t KS = stage, VS = stage + 8192;

        // ---- S = Q @ K^T (log2 domain) ----
        float s[8][4];
#pragma unroll
        for (int nt = 0; nt < 8; nt++)
#pragma unroll
            for (int j = 0; j < 4; j++) s[nt][j] = 0.f;

#pragma unroll
        for (int ks = 0; ks < 4; ks++) {
            const int g = ks * 2 + (sub >> 1);
            uint32_t ah[4];
            {
                int row = wid * 16 + ((sub & 1) << 3) + l7;
                ldm_x4(ah, QH + SW(row, g));
            }
#pragma unroll
            for (int nb = 0; nb < 4; nb++) {
                int row = nb * 16 + ((sub & 1) << 3) + l7;
                uint32_t kq[4];
                ldm_x4(kq, KS + SW(row, g));
                mma16816(s[nb*2],   ah, kq[0], kq[2]);
                mma16816(s[nb*2+1], ah, kq[1], kq[3]);
            }
        }

        // ---- online softmax, exp2 domain ----
        float rmax0 = -1e30f, rmax1 = -1e30f;
#pragma unroll
        for (int nt = 0; nt < 8; nt++) {
            rmax0 = fmaxf(rmax0, fmaxf(s[nt][0], s[nt][1]));
            rmax1 = fmaxf(rmax1, fmaxf(s[nt][2], s[nt][3]));
        }
        rmax0 = fmaxf(rmax0, __shfl_xor_sync(~0u, rmax0, 1));
        rmax0 = fmaxf(rmax0, __shfl_xor_sync(~0u, rmax0, 2));
        rmax1 = fmaxf(rmax1, __shfl_xor_sync(~0u, rmax1, 1));
        rmax1 = fmaxf(rmax1, __shfl_xor_sync(~0u, rmax1, 2));

        float mn0 = fmaxf(m0, rmax0), mn1 = fmaxf(m1, rmax1);
        float corr0 = ex2(m0 - mn0), corr1 = ex2(m1 - mn1);
        m0 = mn0; m1 = mn1;

        float rs0 = 0.f, rs1 = 0.f;
#pragma unroll
        for (int nt = 0; nt < 8; nt++) {
            s[nt][0] = ex2(s[nt][0] - m0);
            s[nt][1] = ex2(s[nt][1] - m0);
            s[nt][2] = ex2(s[nt][2] - m1);
            s[nt][3] = ex2(s[nt][3] - m1);
            rs0 += s[nt][0] + s[nt][1];
            rs1 += s[nt][2] + s[nt][3];
        }
        rs0 += __shfl_xor_sync(~0u, rs0, 1); rs0 += __shfl_xor_sync(~0u, rs0, 2);
        rs1 += __shfl_xor_sync(~0u, rs1, 1); rs1 += __shfl_xor_sync(~0u, rs1, 2);
        l0 = l0 * corr0 + rs0;
        l1 = l1 * corr1 + rs1;
#pragma unroll
        for (int nt = 0; nt < 8; nt++) {
            o[nt][0] *= corr0; o[nt][1] *= corr0;
            o[nt][2] *= corr1; o[nt][3] *= corr1;
        }

        // ---- O += P @ V ----
#pragma unroll
        for (int kvt = 0; kvt < 4; kvt++) {
            const float* t0 = s[kvt*2];
            const float* t1 = s[kvt*2+1];
            uint32_t ph[4];
            ph[0] = pack_h2(t0[0], t0[1]);
            ph[1] = pack_h2(t0[2], t0[3]);
            ph[2] = pack_h2(t1[0], t1[1]);
            ph[3] = pack_h2(t1[2], t1[3]);
            int row = kvt * 16 + ((sub & 1) << 3) + l7;
#pragma unroll
            for (int db = 0; db < 4; db++) {
                int g = db * 2 + (sub >> 1);
                uint32_t vq[4];
                ldm_x4_t(vq, VS + SW(row, g));
                mma16816(o[db*2],   ph, vq[0], vq[1]);
                mma16816(o[db*2+1], ph, vq[2], vq[3]);
            }
        }
    }

    // ---- finalize: divide by l, write single fp16 ----
    float inv0 = 1.f / l0, inv1 = 1.f / l1;
    int row0 = q0 + wid * 16 + rq;
#pragma unroll
    for (int nt = 0; nt < 8; nt++) {
        int col = nt * 8 + cq;
        *(__half2*)(g_oh + hbase + (size_t)row0 * DD + col) =
            __floats2half2_rn(o[nt][0] * inv0, o[nt][1] * inv0);
        *(__half2*)(g_oh + hbase + (size_t)(row0 + 8) * DD + col) =
            __floats2half2_rn(o[nt][2] * inv1, o[nt][3] * inv1);
    }
}

// ---------------------------------------------------------------------------
extern "C" void kernel_launch(void* const* d_in, const int* in_sizes, int n_in,
                              void* d_out, int out_size)
{
    const float* x   = (const float*)d_in[0];
    const float* qw  = (const float*)d_in[1];
    const float* qb  = (const float*)d_in[2];
    const float* kw  = (const float*)d_in[3];
    const float* kb  = (const float*)d_in[4];
    const float* vw  = (const float*)d_in[5];
    const float* vb  = (const float*)d_in[6];
    const float* ow  = (const float*)d_in[7];
    const float* ob  = (const float*)d_in[8];
    const float* qlg = (const float*)d_in[9];
    const float* qlb = (const float*)d_in[10];
    const float* klg = (const float*)d_in[11];
    const float* klb = (const float*)d_in[12];
    float* out = (float*)d_out;

    cudaFuncSetAttribute(qkv_hmma_kernel,
                         cudaFuncAttributeMaxDynamicSharedMemorySize, GEMM_SMEM);
    cudaFuncSetAttribute(oproj_hmma_kernel,
                         cudaFuncAttributeMaxDynamicSharedMemorySize, GEMM_SMEM);
    cudaFuncSetAttribute(flash_hmma_kernel,
                         cudaFuncAttributeMaxDynamicSharedMemorySize, FLASH_SMEM);

    conv_kernel<<<dim3(DD*DD/1024, 8), 256>>>(x, qw, kw, vw, ow);

    qkv_hmma_kernel<<<dim3(DD/128, NTOK/128, 3), 256, GEMM_SMEM>>>(
        qb, kb, vb, qlg, qlb, klg, klb);
    flash_hmma_kernel<<<dim3(SS/64, HH, BB), 128, FLASH_SMEM>>>();
    oproj_hmma_kernel<<<dim3(DD/128, NTOK/128), 256, GEMM_SMEM>>>(ob, out);
}